// round 3
// baseline (speedup 1.0000x reference)
#include <cuda_runtime.h>
#include <math.h>

// Problem constants
#define BS   128
#define NW   80
#define NP   128
#define NQ   36
#define DIM  768
#define TAU_INV 100.0f

#define PT   4            // patches per K2 block
#define NT   144          // PT*NQ columns per tile
#define FS   148          // F row stride in smem (4-aligned, odd/32-friendly)

// Scratch (device globals: no allocation allowed)
__device__ float g_pl [NP*NQ*DIM];    // 4608 x 768  : patch @ L^T
__device__ float g_wl [BS*NP*NQ];     // word_level [b][p][q]
__device__ float g_plv[BS*NW*NP];     // patch_level [b][w][p]
__device__ float g_sim[BS*NP];        // sim [b][p]

// ---------------------------------------------------------------------------
// K1: pl[i][d] = sum_e patch2d[i][e] * L[d][e]    (M=4608, N=768, K=768)
// Tile 64x128, KT=16, 4x8 per thread, reg-prefetch double buffering.
// ---------------------------------------------------------------------------
#define K1_AS 20
__global__ void __launch_bounds__(256) k1_plgemm(const float* __restrict__ patch,
                                                 const float* __restrict__ L) {
    __shared__ float As[64 * K1_AS];
    __shared__ float Bs[128 * K1_AS];
    const int tid = threadIdx.x;
    const int tx = tid & 15, ty = tid >> 4;
    const int m0 = blockIdx.y * 64;
    const int n0 = blockIdx.x * 128;
    const float* Ap = patch + (size_t)m0 * DIM;
    const float* Bp = L + (size_t)n0 * DIM;

    const int ar = tid >> 2;          // 0..63
    const int ac = (tid & 3) << 2;    // 0,4,8,12

    float4 pa, pb0, pb1;
    pa  = *(const float4*)&Ap[ar * DIM + ac];
    pb0 = *(const float4*)&Bp[ar * DIM + ac];
    pb1 = *(const float4*)&Bp[(ar + 64) * DIM + ac];

    float acc[4][8];
#pragma unroll
    for (int i = 0; i < 4; i++)
#pragma unroll
        for (int j = 0; j < 8; j++) acc[i][j] = 0.0f;

    for (int kc = 0; kc < DIM / 16; kc++) {
        __syncthreads();
        *(float4*)&As[ar * K1_AS + ac] = pa;
        *(float4*)&Bs[ar * K1_AS + ac] = pb0;
        *(float4*)&Bs[(ar + 64) * K1_AS + ac] = pb1;
        __syncthreads();
        if (kc < DIM / 16 - 1) {
            const int kn = (kc + 1) * 16 + ac;
            pa  = *(const float4*)&Ap[ar * DIM + kn];
            pb0 = *(const float4*)&Bp[ar * DIM + kn];
            pb1 = *(const float4*)&Bp[(ar + 64) * DIM + kn];
        }
#pragma unroll
        for (int k4 = 0; k4 < 4; k4++) {
            float4 a4[4], b4[8];
#pragma unroll
            for (int i = 0; i < 4; i++) a4[i] = *(float4*)&As[(ty + 16 * i) * K1_AS + 4 * k4];
#pragma unroll
            for (int j = 0; j < 8; j++) b4[j] = *(float4*)&Bs[(tx + 16 * j) * K1_AS + 4 * k4];
#pragma unroll
            for (int i = 0; i < 4; i++)
#pragma unroll
                for (int j = 0; j < 8; j++)
                    acc[i][j] += a4[i].x * b4[j].x + a4[i].y * b4[j].y +
                                 a4[i].z * b4[j].z + a4[i].w * b4[j].w;
        }
    }
#pragma unroll
    for (int i = 0; i < 4; i++)
#pragma unroll
        for (int j = 0; j < 8; j++)
            g_pl[(size_t)(m0 + ty + 16 * i) * DIM + n0 + tx + 16 * j] = acc[i][j];
}

// ---------------------------------------------------------------------------
// K2: per (b, patch-tile) block:
//     F[80][144] = word[b] @ pl[ptile]^T      (M=80, N=144, K=768)
//   then fused epilogue:
//     word_level[b,p,q]  = sum_w softmax_w(F/tau)[w] * (Ww @ F)[w]   (per column)
//     patch_level[b,w,p] = sum_q softmax_q(F/tau)[q] * (F . Wp^T)[q] (per row,p)
// ---------------------------------------------------------------------------
__global__ void __launch_bounds__(256) k2_fine(const float* __restrict__ word,
                                               const float* __restrict__ Ww,
                                               const float* __restrict__ Wp) {
    extern __shared__ float sm[];
    float* Fs   = sm;            // 80*148 = 11840
    float* SC   = sm + 11840;    // 11840: GEMM stage (As 2880 | Bs 5184), later G
    float* Wws  = sm + 23680;    // 6400
    float* Wps  = sm + 30080;    // 1296
    float* cmax = sm + 31376;    // 144
    float* csum = sm + 31520;    // 144  (total 31664 floats = 126656 B)

    const int tid = threadIdx.x;
    const int tx = tid & 15, ty = tid >> 4;
    const int b = blockIdx.y, pb = blockIdx.x;

    // stage small weight matrices
    for (int i = tid; i < 1600; i += 256) ((float4*)Wws)[i] = ((const float4*)Ww)[i];
    for (int i = tid; i < 324;  i += 256) ((float4*)Wps)[i] = ((const float4*)Wp)[i];

    const float* Aw = word + (size_t)b * NW * DIM;
    const float* Bp = g_pl + (size_t)pb * NT * DIM;   // 144 contiguous rows

    float* As = SC;            // [80][36]
    float* Bs = SC + 2880;     // [144][36]

    const int fr_ = tid >> 3;           // 0..31
    const int fc_ = (tid & 7) << 2;     // 0..28

    float4 pa0, pa1, pa2, pq0, pq1, pq2, pq3, pq4;
    {
        pa0 = *(const float4*)&Aw[(fr_) * DIM + fc_];
        pa1 = *(const float4*)&Aw[(fr_ + 32) * DIM + fc_];
        if (tid < 128) pa2 = *(const float4*)&Aw[(fr_ + 64) * DIM + fc_];
        pq0 = *(const float4*)&Bp[(fr_) * DIM + fc_];
        pq1 = *(const float4*)&Bp[(fr_ + 32) * DIM + fc_];
        pq2 = *(const float4*)&Bp[(fr_ + 64) * DIM + fc_];
        pq3 = *(const float4*)&Bp[(fr_ + 96) * DIM + fc_];
        if (tid < 128) pq4 = *(const float4*)&Bp[(fr_ + 128) * DIM + fc_];
    }

    float acc[5][9];
#pragma unroll
    for (int i = 0; i < 5; i++)
#pragma unroll
        for (int j = 0; j < 9; j++) acc[i][j] = 0.0f;

    for (int kc = 0; kc < DIM / 32; kc++) {
        __syncthreads();
        *(float4*)&As[fr_ * 36 + fc_] = pa0;
        *(float4*)&As[(fr_ + 32) * 36 + fc_] = pa1;
        if (tid < 128) *(float4*)&As[(fr_ + 64) * 36 + fc_] = pa2;
        *(float4*)&Bs[fr_ * 36 + fc_] = pq0;
        *(float4*)&Bs[(fr_ + 32) * 36 + fc_] = pq1;
        *(float4*)&Bs[(fr_ + 64) * 36 + fc_] = pq2;
        *(float4*)&Bs[(fr_ + 96) * 36 + fc_] = pq3;
        if (tid < 128) *(float4*)&Bs[(fr_ + 128) * 36 + fc_] = pq4;
        __syncthreads();
        if (kc < DIM / 32 - 1) {
            const int kn = (kc + 1) * 32 + fc_;
            pa0 = *(const float4*)&Aw[(fr_) * DIM + kn];
            pa1 = *(const float4*)&Aw[(fr_ + 32) * DIM + kn];
            if (tid < 128) pa2 = *(const float4*)&Aw[(fr_ + 64) * DIM + kn];
            pq0 = *(const float4*)&Bp[(fr_) * DIM + kn];
            pq1 = *(const float4*)&Bp[(fr_ + 32) * DIM + kn];
            pq2 = *(const float4*)&Bp[(fr_ + 64) * DIM + kn];
            pq3 = *(const float4*)&Bp[(fr_ + 96) * DIM + kn];
            if (tid < 128) pq4 = *(const float4*)&Bp[(fr_ + 128) * DIM + kn];
        }
#pragma unroll 2
        for (int k4 = 0; k4 < 8; k4++) {
            float4 a4[5], b4[9];
#pragma unroll
            for (int i = 0; i < 5; i++) a4[i] = *(float4*)&As[(ty + 16 * i) * 36 + 4 * k4];
#pragma unroll
            for (int j = 0; j < 9; j++) b4[j] = *(float4*)&Bs[(tx + 16 * j) * 36 + 4 * k4];
#pragma unroll
            for (int i = 0; i < 5; i++)
#pragma unroll
                for (int j = 0; j < 9; j++)
                    acc[i][j] += a4[i].x * b4[j].x + a4[i].y * b4[j].y +
                                 a4[i].z * b4[j].z + a4[i].w * b4[j].w;
        }
    }

    // F tile -> smem
#pragma unroll
    for (int i = 0; i < 5; i++)
#pragma unroll
        for (int j = 0; j < 9; j++)
            Fs[(ty + 16 * i) * FS + tx + 16 * j] = acc[i][j];
    __syncthreads();

    // column softmax stats (over w)
    if (tid < NT) {
        float m = -1e30f;
        for (int w = 0; w < NW; w++) m = fmaxf(m, Fs[w * FS + tid]);
        float s = 0.0f;
        for (int w = 0; w < NW; w++) s += __expf((Fs[w * FS + tid] - m) * TAU_INV);
        cmax[tid] = m;
        csum[tid] = s;
    }

    // G = Ww @ F  (80x80 * 80x144), into SC (stage no longer needed)
    float ga[5][9];
#pragma unroll
    for (int i = 0; i < 5; i++)
#pragma unroll
        for (int j = 0; j < 9; j++) ga[i][j] = 0.0f;
    for (int v4 = 0; v4 < 20; v4++) {
        float aa[5][4];
#pragma unroll
        for (int i = 0; i < 5; i++) {
            float4 a4 = *(float4*)&Wws[(ty + 16 * i) * 80 + 4 * v4];
            aa[i][0] = a4.x; aa[i][1] = a4.y; aa[i][2] = a4.z; aa[i][3] = a4.w;
        }
#pragma unroll
        for (int vv = 0; vv < 4; vv++) {
            const int v = 4 * v4 + vv;
            float bv[9];
#pragma unroll
            for (int j = 0; j < 9; j++) bv[j] = Fs[v * FS + tx + 16 * j];
#pragma unroll
            for (int i = 0; i < 5; i++)
#pragma unroll
                for (int j = 0; j < 9; j++) ga[i][j] += aa[i][vv] * bv[j];
        }
    }
    __syncthreads();   // stage fully consumed; cmax/csum published
#pragma unroll
    for (int i = 0; i < 5; i++)
#pragma unroll
        for (int j = 0; j < 9; j++)
            SC[(ty + 16 * i) * FS + tx + 16 * j] = ga[i][j];
    __syncthreads();

    // word_level[b, pb*4 + j/36, j%36]
    if (tid < NT) {
        const float m = cmax[tid];
        const float s = csum[tid];
        float a = 0.0f;
        for (int w = 0; w < NW; w++)
            a += __expf((Fs[w * FS + tid] - m) * TAU_INV) * SC[w * FS + tid];
        g_wl[(size_t)b * (NP * NQ) + pb * NT + tid] = a / s;
    }

    // patch_level[b, w, pb*4 + p]
    for (int pr = tid; pr < NW * PT; pr += 256) {
        const int w = pr >> 2, p = pr & 3;
        const float* frow = &Fs[w * FS + p * NQ];
        float fr[NQ];
#pragma unroll
        for (int c = 0; c < 9; c++) *(float4*)&fr[4 * c] = *(const float4*)&frow[4 * c];
        float m = fr[0];
#pragma unroll
        for (int q = 1; q < NQ; q++) m = fmaxf(m, fr[q]);
        float s = 0.0f, a = 0.0f;
        for (int q = 0; q < NQ; q++) {
            float u = 0.0f;
#pragma unroll
            for (int rv = 0; rv < 9; rv++) {
                float4 w4 = *(float4*)&Wps[q * NQ + 4 * rv];
                u += w4.x * fr[4 * rv] + w4.y * fr[4 * rv + 1] +
                     w4.z * fr[4 * rv + 2] + w4.w * fr[4 * rv + 3];
            }
            const float e = __expf((fr[q] - m) * TAU_INV);
            s += e;
            a += e * u;
        }
        g_plv[(size_t)b * (NW * NP) + w * NP + pb * PT + p] = a / s;
    }
}

// ---------------------------------------------------------------------------
// K3: per b: s2p/p2w second-level reductions -> sim[b][p]
// ---------------------------------------------------------------------------
__global__ void __launch_bounds__(128) k3_stage2(const float* __restrict__ Ww2,
                                                 const float* __restrict__ Wp2) {
    extern __shared__ float sm[];
    float* wls = sm;            // 4608  : word_level[b]  [p][q]
    float* pls = sm + 4608;     // 10240 : patch_level[b] [w][p]
    float* W2s = sm + 14848;    // 6400
    float* P2s = sm + 21248;    // 1296  (total 22544 floats)
    const int b = blockIdx.x, tid = threadIdx.x;

    const float4* s1 = (const float4*)(g_wl + (size_t)b * (NP * NQ));
    for (int i = tid; i < 1152; i += 128) ((float4*)wls)[i] = s1[i];
    const float4* s2 = (const float4*)(g_plv + (size_t)b * (NW * NP));
    for (int i = tid; i < 2560; i += 128) ((float4*)pls)[i] = s2[i];
    for (int i = tid; i < 1600; i += 128) ((float4*)W2s)[i] = ((const float4*)Ww2)[i];
    for (int i = tid; i < 324;  i += 128) ((float4*)P2s)[i] = ((const float4*)Wp2)[i];
    __syncthreads();

    const int p = tid;
    // s2p over q=36
    float fr[NQ];
#pragma unroll
    for (int c = 0; c < 9; c++) *(float4*)&fr[4 * c] = *(float4*)&wls[p * NQ + 4 * c];
    float m = fr[0];
#pragma unroll
    for (int q = 1; q < NQ; q++) m = fmaxf(m, fr[q]);
    float s = 0.0f, a = 0.0f;
    for (int q = 0; q < NQ; q++) {
        float u = 0.0f;
#pragma unroll
        for (int rv = 0; rv < 9; rv++) {
            float4 w4 = *(float4*)&P2s[q * NQ + 4 * rv];
            u += w4.x * fr[4 * rv] + w4.y * fr[4 * rv + 1] +
                 w4.z * fr[4 * rv + 2] + w4.w * fr[4 * rv + 3];
        }
        const float e = __expf((fr[q] - m) * TAU_INV);
        s += e; a += e * u;
    }
    const float s2p = a / s;

    // p2w over w=80
    float fw[NW];
    for (int w = 0; w < NW; w++) fw[w] = pls[w * NP + p];
    m = fw[0];
#pragma unroll
    for (int w = 1; w < NW; w++) m = fmaxf(m, fw[w]);
    s = 0.0f; a = 0.0f;
    for (int w = 0; w < NW; w++) {
        float u = 0.0f;
#pragma unroll
        for (int v4 = 0; v4 < 20; v4++) {
            float4 w4 = *(float4*)&W2s[w * NW + 4 * v4];
            u += w4.x * fw[4 * v4] + w4.y * fw[4 * v4 + 1] +
                 w4.z * fw[4 * v4 + 2] + w4.w * fw[4 * v4 + 3];
        }
        const float e = __expf((fw[w] - m) * TAU_INV);
        s += e; a += e * u;
    }
    const float p2w = a / s;

    g_sim[b * NP + p] = 0.5f * (s2p + p2w);
}

// ---------------------------------------------------------------------------
// K4: loss = -mean_i( sim[i][i] - 0.5*(lse_row_i + lse_col_i) )
// ---------------------------------------------------------------------------
__global__ void __launch_bounds__(128) k4_loss(float* __restrict__ out) {
    extern __shared__ float sm[];
    float* sims = sm;             // 128*129 (padded)
    float* red  = sm + 128 * 129; // 128
    const int tid = threadIdx.x;
    for (int i = tid; i < BS * NP; i += 128) {
        const int r = i >> 7, c = i & 127;
        sims[r * 129 + c] = g_sim[i];
    }
    __syncthreads();
    const int i = tid;
    float m = -1e30f;
    for (int j = 0; j < 128; j++) m = fmaxf(m, sims[i * 129 + j]);
    float s = 0.0f;
    for (int j = 0; j < 128; j++) s += expf(sims[i * 129 + j] - m);
    const float lser = m + logf(s);
    m = -1e30f;
    for (int j = 0; j < 128; j++) m = fmaxf(m, sims[j * 129 + i]);
    s = 0.0f;
    for (int j = 0; j < 128; j++) s += expf(sims[j * 129 + i] - m);
    const float lsec = m + logf(s);
    red[i] = sims[i * 129 + i] - 0.5f * (lser + lsec);
    __syncthreads();
    if (tid == 0) {
        float t = 0.0f;
        for (int j = 0; j < 128; j++) t += red[j];
        out[0] = -t / 128.0f;
    }
}

// ---------------------------------------------------------------------------
extern "C" void kernel_launch(void* const* d_in, const int* in_sizes, int n_in,
                              void* d_out, int out_size) {
    const float* patch = (const float*)d_in[0];  // (128, 36, 768)
    const float* word  = (const float*)d_in[1];  // (128, 80, 768)
    const float* L     = (const float*)d_in[2];  // (768, 768)
    const float* Ww    = (const float*)d_in[3];  // (80, 80)
    const float* Wp    = (const float*)d_in[4];  // (36, 36)
    const float* Ww2   = (const float*)d_in[5];  // (80, 80)
    const float* Wp2   = (const float*)d_in[6];  // (36, 36)
    float* out = (float*)d_out;

    const int smem_k2 = 31664 * 4;
    const int smem_k3 = 22544 * 4;
    const int smem_k4 = (128 * 129 + 128) * 4;
    cudaFuncSetAttribute(k2_fine,  cudaFuncAttributeMaxDynamicSharedMemorySize, smem_k2);
    cudaFuncSetAttribute(k3_stage2, cudaFuncAttributeMaxDynamicSharedMemorySize, smem_k3);
    cudaFuncSetAttribute(k4_loss,  cudaFuncAttributeMaxDynamicSharedMemorySize, smem_k4);

    k1_plgemm<<<dim3(6, 72), 256>>>(patch, L);
    k2_fine<<<dim3(NP / PT, BS), 256, smem_k2>>>(word, Ww, Wp);
    k3_stage2<<<BS, 128, smem_k3>>>(Ww2, Wp2);
    k4_loss<<<1, 128, smem_k4>>>(out);
}

// round 4
// speedup vs baseline: 1.1647x; 1.1647x over previous
#include <cuda_runtime.h>
#include <math.h>
#include <stdint.h>

// Problem constants
#define BS   128
#define NW   80
#define NP   128
#define NQ   36
#define DIM  768
#define TAU_INV 100.0f

#define PT   4            // patches per K2 block
#define NT   144          // PT*NQ columns per tile
#define FS   148          // F row stride in smem

// Scratch (device globals: no allocation allowed)
__device__ float g_pl [NP*NQ*DIM];    // 4608 x 768  : patch @ L^T
__device__ float g_wl [BS*NP*NQ];     // word_level [b][p][q]
__device__ float g_plv[BS*NW*NP];     // patch_level [b][w][p]
__device__ float g_sim[BS*NP];        // sim [b][p]

// ---------------------------------------------------------------------------
// tf32 helpers
// ---------------------------------------------------------------------------
__device__ __forceinline__ float tf32_rna(float x) {
    uint32_t u;
    asm("cvt.rna.tf32.f32 %0, %1;" : "=r"(u) : "f"(x));
    return __uint_as_float(u);
}
__device__ __forceinline__ void split4(float4 v, float4& h, float4& l) {
    h.x = tf32_rna(v.x); l.x = tf32_rna(v.x - h.x);
    h.y = tf32_rna(v.y); l.y = tf32_rna(v.y - h.y);
    h.z = tf32_rna(v.z); l.z = tf32_rna(v.z - h.z);
    h.w = tf32_rna(v.w); l.w = tf32_rna(v.w - h.w);
}
__device__ __forceinline__ void mma_tf32(float4& d,
    uint32_t a0, uint32_t a1, uint32_t a2, uint32_t a3,
    uint32_t b0, uint32_t b1) {
    asm volatile(
        "mma.sync.aligned.m16n8k8.row.col.f32.tf32.tf32.f32 "
        "{%0,%1,%2,%3}, {%4,%5,%6,%7}, {%8,%9}, {%0,%1,%2,%3};\n"
        : "+f"(d.x), "+f"(d.y), "+f"(d.z), "+f"(d.w)
        : "r"(a0), "r"(a1), "r"(a2), "r"(a3), "r"(b0), "r"(b1));
}

// ---------------------------------------------------------------------------
// K1: pl[i][d] = sum_e patch2d[i][e] * L[d][e]    (M=4608, N=768, K=768)
// ---------------------------------------------------------------------------
#define K1_AS 20
__global__ void __launch_bounds__(256) k1_plgemm(const float* __restrict__ patch,
                                                 const float* __restrict__ L) {
    __shared__ float As[64 * K1_AS];
    __shared__ float Bs[128 * K1_AS];
    const int tid = threadIdx.x;
    const int tx = tid & 15, ty = tid >> 4;
    const int m0 = blockIdx.y * 64;
    const int n0 = blockIdx.x * 128;
    const float* Ap = patch + (size_t)m0 * DIM;
    const float* Bp = L + (size_t)n0 * DIM;

    const int ar = tid >> 2;          // 0..63
    const int ac = (tid & 3) << 2;    // 0,4,8,12

    float4 pa, pb0, pb1;
    pa  = *(const float4*)&Ap[ar * DIM + ac];
    pb0 = *(const float4*)&Bp[ar * DIM + ac];
    pb1 = *(const float4*)&Bp[(ar + 64) * DIM + ac];

    float acc[4][8];
#pragma unroll
    for (int i = 0; i < 4; i++)
#pragma unroll
        for (int j = 0; j < 8; j++) acc[i][j] = 0.0f;

    for (int kc = 0; kc < DIM / 16; kc++) {
        __syncthreads();
        *(float4*)&As[ar * K1_AS + ac] = pa;
        *(float4*)&Bs[ar * K1_AS + ac] = pb0;
        *(float4*)&Bs[(ar + 64) * K1_AS + ac] = pb1;
        __syncthreads();
        if (kc < DIM / 16 - 1) {
            const int kn = (kc + 1) * 16 + ac;
            pa  = *(const float4*)&Ap[ar * DIM + kn];
            pb0 = *(const float4*)&Bp[ar * DIM + kn];
            pb1 = *(const float4*)&Bp[(ar + 64) * DIM + kn];
        }
#pragma unroll
        for (int k4 = 0; k4 < 4; k4++) {
            float4 a4[4], b4[8];
#pragma unroll
            for (int i = 0; i < 4; i++) a4[i] = *(float4*)&As[(ty + 16 * i) * K1_AS + 4 * k4];
#pragma unroll
            for (int j = 0; j < 8; j++) b4[j] = *(float4*)&Bs[(tx + 16 * j) * K1_AS + 4 * k4];
#pragma unroll
            for (int i = 0; i < 4; i++)
#pragma unroll
                for (int j = 0; j < 8; j++)
                    acc[i][j] += a4[i].x * b4[j].x + a4[i].y * b4[j].y +
                                 a4[i].z * b4[j].z + a4[i].w * b4[j].w;
        }
    }
#pragma unroll
    for (int i = 0; i < 4; i++)
#pragma unroll
        for (int j = 0; j < 8; j++)
            g_pl[(size_t)(m0 + ty + 16 * i) * DIM + n0 + tx + 16 * j] = acc[i][j];
}

// ---------------------------------------------------------------------------
// K2 v2: tf32 tensor-core mainloop (2-split, 3 products), fused epilogue.
//   F[80][144] = word[b] @ pl[ptile]^T   (M=80, N=144, K=768)
// 320 threads = 10 warps; warp (ms,ns): rows [16ms,16ms+16), cols [72ns,72ns+72)
// ---------------------------------------------------------------------------
__global__ void __launch_bounds__(320) k2_fine(const float* __restrict__ word,
                                               const float* __restrict__ Ww,
                                               const float* __restrict__ Wp) {
    extern __shared__ float sm[];
    float* Fs    = sm;            // 80*148 = 11840
    float* As_hi = sm + 11840;    // 80*36 = 2880
    float* As_lo = sm + 14720;    // 2880
    float* Bs_hi = sm + 17600;    // 144*36 = 5184
    float* Bs_lo = sm + 22784;    // 5184 (stage ends 27968)
    float* SC    = sm + 11840;    // alias over stage after mainloop (11840 used)
    float* Wws   = sm + 27968;    // 6400
    float* Wps   = sm + 34368;    // 1296
    float* cmax  = sm + 35664;    // 144
    float* csum  = sm + 35808;    // 144 -> total 35952 floats = 143808 B

    const int tid  = threadIdx.x;
    const int lane = tid & 31, wid = tid >> 5;
    const int g  = lane >> 2, t4 = lane & 3;
    const int ms = wid >> 1,  ns = wid & 1;        // wid 0..9
    const int b = blockIdx.y, pb = blockIdx.x;

    // stage small weight matrices
    for (int i = tid; i < 1600; i += 320) ((float4*)Wws)[i] = ((const float4*)Ww)[i];
    for (int i = tid; i < 324;  i += 320) ((float4*)Wps)[i] = ((const float4*)Wp)[i];

    const float* Aw = word + (size_t)b * NW * DIM;
    const float* Bp = g_pl + (size_t)pb * NT * DIM;   // 144 contiguous rows

    // --- prefetch chunk 0 (fp32) ---
    float4 pa[2], pbv[4];
#pragma unroll
    for (int j = 0; j < 2; j++) {
        const int i = tid + 320 * j, r = i >> 3, cg = i & 7;   // i < 640
        pa[j] = *(const float4*)&Aw[r * DIM + 4 * cg];
    }
#pragma unroll
    for (int j = 0; j < 4; j++) {
        const int i = tid + 320 * j;
        if (i < 1152) {
            const int r = i >> 3, cg = i & 7;
            pbv[j] = *(const float4*)&Bp[r * DIM + 4 * cg];
        }
    }

    float4 acc[9];
#pragma unroll
    for (int j = 0; j < 9; j++) acc[j] = make_float4(0.f, 0.f, 0.f, 0.f);

    for (int kc = 0; kc < 24; kc++) {
        __syncthreads();
        // split + store stage
#pragma unroll
        for (int j = 0; j < 2; j++) {
            const int i = tid + 320 * j, r = i >> 3, cg = i & 7;
            float4 h, l; split4(pa[j], h, l);
            *(float4*)&As_hi[r * 36 + 4 * cg] = h;
            *(float4*)&As_lo[r * 36 + 4 * cg] = l;
        }
#pragma unroll
        for (int j = 0; j < 4; j++) {
            const int i = tid + 320 * j;
            if (i < 1152) {
                const int r = i >> 3, cg = i & 7;
                float4 h, l; split4(pbv[j], h, l);
                *(float4*)&Bs_hi[r * 36 + 4 * cg] = h;
                *(float4*)&Bs_lo[r * 36 + 4 * cg] = l;
            }
        }
        __syncthreads();
        // prefetch next chunk
        if (kc < 23) {
            const int kn = (kc + 1) * 32;
#pragma unroll
            for (int j = 0; j < 2; j++) {
                const int i = tid + 320 * j, r = i >> 3, cg = i & 7;
                pa[j] = *(const float4*)&Aw[r * DIM + kn + 4 * cg];
            }
#pragma unroll
            for (int j = 0; j < 4; j++) {
                const int i = tid + 320 * j;
                if (i < 1152) {
                    const int r = i >> 3, cg = i & 7;
                    pbv[j] = *(const float4*)&Bp[r * DIM + kn + 4 * cg];
                }
            }
        }
        // compute: 4 k8-steps
#pragma unroll
        for (int kk = 0; kk < 4; kk++) {
            const int ar = (16 * ms + g) * 36 + kk * 8 + t4;
            const uint32_t ah0 = __float_as_uint(As_hi[ar]);
            const uint32_t ah1 = __float_as_uint(As_hi[ar + 8 * 36]);
            const uint32_t ah2 = __float_as_uint(As_hi[ar + 4]);
            const uint32_t ah3 = __float_as_uint(As_hi[ar + 8 * 36 + 4]);
            const uint32_t al0 = __float_as_uint(As_lo[ar]);
            const uint32_t al1 = __float_as_uint(As_lo[ar + 8 * 36]);
            const uint32_t al2 = __float_as_uint(As_lo[ar + 4]);
            const uint32_t al3 = __float_as_uint(As_lo[ar + 8 * 36 + 4]);
#pragma unroll
            for (int nt = 0; nt < 9; nt++) {
                const int br = (72 * ns + 8 * nt + g) * 36 + kk * 8 + t4;
                const uint32_t bh0 = __float_as_uint(Bs_hi[br]);
                const uint32_t bh1 = __float_as_uint(Bs_hi[br + 4]);
                const uint32_t bl0 = __float_as_uint(Bs_lo[br]);
                const uint32_t bl1 = __float_as_uint(Bs_lo[br + 4]);
                mma_tf32(acc[nt], ah0, ah1, ah2, ah3, bh0, bh1);
                mma_tf32(acc[nt], ah0, ah1, ah2, ah3, bl0, bl1);
                mma_tf32(acc[nt], al0, al1, al2, al3, bh0, bh1);
            }
        }
    }

    // F tile -> smem (C fragment layout: rows g/g+8, cols 2t4, 2t4+1)
#pragma unroll
    for (int nt = 0; nt < 9; nt++) {
        const int row = 16 * ms + g, col = 72 * ns + 8 * nt + 2 * t4;
        Fs[row * FS + col]           = acc[nt].x;
        Fs[row * FS + col + 1]       = acc[nt].y;
        Fs[(row + 8) * FS + col]     = acc[nt].z;
        Fs[(row + 8) * FS + col + 1] = acc[nt].w;
    }
    __syncthreads();

    // column softmax stats (over w)
    if (tid < NT) {
        float m = -1e30f;
        for (int w = 0; w < NW; w++) m = fmaxf(m, Fs[w * FS + tid]);
        float s = 0.0f;
        for (int w = 0; w < NW; w++) s += __expf((Fs[w * FS + tid] - m) * TAU_INV);
        cmax[tid] = m;
        csum[tid] = s;
    }

    // G = Ww @ F  (80x80 * 80x144) on first 256 threads, into SC
    float ga[5][9];
    if (tid < 256) {
        const int tx = tid & 15, ty = tid >> 4;
#pragma unroll
        for (int i = 0; i < 5; i++)
#pragma unroll
            for (int j = 0; j < 9; j++) ga[i][j] = 0.0f;
        for (int v4 = 0; v4 < 20; v4++) {
            float aa[5][4];
#pragma unroll
            for (int i = 0; i < 5; i++) {
                float4 a4 = *(float4*)&Wws[(ty + 16 * i) * 80 + 4 * v4];
                aa[i][0] = a4.x; aa[i][1] = a4.y; aa[i][2] = a4.z; aa[i][3] = a4.w;
            }
#pragma unroll
            for (int vv = 0; vv < 4; vv++) {
                const int v = 4 * v4 + vv;
                float bv[9];
#pragma unroll
                for (int j = 0; j < 9; j++) bv[j] = Fs[v * FS + tx + 16 * j];
#pragma unroll
                for (int i = 0; i < 5; i++)
#pragma unroll
                    for (int j = 0; j < 9; j++) ga[i][j] += aa[i][vv] * bv[j];
            }
        }
    }
    __syncthreads();   // stage fully consumed; cmax/csum published
    if (tid < 256) {
        const int tx = tid & 15, ty = tid >> 4;
#pragma unroll
        for (int i = 0; i < 5; i++)
#pragma unroll
            for (int j = 0; j < 9; j++)
                SC[(ty + 16 * i) * FS + tx + 16 * j] = ga[i][j];
    }
    __syncthreads();

    // word_level[b, pb*4 + j/36, j%36]
    if (tid < NT) {
        const float m = cmax[tid];
        const float s = csum[tid];
        float a = 0.0f;
        for (int w = 0; w < NW; w++)
            a += __expf((Fs[w * FS + tid] - m) * TAU_INV) * SC[w * FS + tid];
        g_wl[(size_t)b * (NP * NQ) + pb * NT + tid] = a / s;
    }

    // patch_level[b, w, pb*4 + p]  (NW*PT = 320: one row per thread)
    for (int pr = tid; pr < NW * PT; pr += 320) {
        const int w = pr >> 2, p = pr & 3;
        const float* frow = &Fs[w * FS + p * NQ];
        float fr[NQ];
#pragma unroll
        for (int c = 0; c < 9; c++) *(float4*)&fr[4 * c] = *(const float4*)&frow[4 * c];
        float m = fr[0];
#pragma unroll
        for (int q = 1; q < NQ; q++) m = fmaxf(m, fr[q]);
        float s = 0.0f, a = 0.0f;
        for (int q = 0; q < NQ; q++) {
            float u = 0.0f;
#pragma unroll
            for (int rv = 0; rv < 9; rv++) {
                float4 w4 = *(float4*)&Wps[q * NQ + 4 * rv];
                u += w4.x * fr[4 * rv] + w4.y * fr[4 * rv + 1] +
                     w4.z * fr[4 * rv + 2] + w4.w * fr[4 * rv + 3];
            }
            const float e = __expf((fr[q] - m) * TAU_INV);
            s += e;
            a += e * u;
        }
        g_plv[(size_t)b * (NW * NP) + w * NP + pb * PT + p] = a / s;
    }
}

// ---------------------------------------------------------------------------
// K3: per b: s2p/p2w second-level reductions -> sim[b][p]
// ---------------------------------------------------------------------------
__global__ void __launch_bounds__(128) k3_stage2(const float* __restrict__ Ww2,
                                                 const float* __restrict__ Wp2) {
    extern __shared__ float sm[];
    float* wls = sm;            // 4608
    float* pls = sm + 4608;     // 10240
    float* W2s = sm + 14848;    // 6400
    float* P2s = sm + 21248;    // 1296
    const int b = blockIdx.x, tid = threadIdx.x;

    const float4* s1 = (const float4*)(g_wl + (size_t)b * (NP * NQ));
    for (int i = tid; i < 1152; i += 128) ((float4*)wls)[i] = s1[i];
    const float4* s2 = (const float4*)(g_plv + (size_t)b * (NW * NP));
    for (int i = tid; i < 2560; i += 128) ((float4*)pls)[i] = s2[i];
    for (int i = tid; i < 1600; i += 128) ((float4*)W2s)[i] = ((const float4*)Ww2)[i];
    for (int i = tid; i < 324;  i += 128) ((float4*)P2s)[i] = ((const float4*)Wp2)[i];
    __syncthreads();

    const int p = tid;
    float fr[NQ];
#pragma unroll
    for (int c = 0; c < 9; c++) *(float4*)&fr[4 * c] = *(float4*)&wls[p * NQ + 4 * c];
    float m = fr[0];
#pragma unroll
    for (int q = 1; q < NQ; q++) m = fmaxf(m, fr[q]);
    float s = 0.0f, a = 0.0f;
    for (int q = 0; q < NQ; q++) {
        float u = 0.0f;
#pragma unroll
        for (int rv = 0; rv < 9; rv++) {
            float4 w4 = *(float4*)&P2s[q * NQ + 4 * rv];
            u += w4.x * fr[4 * rv] + w4.y * fr[4 * rv + 1] +
                 w4.z * fr[4 * rv + 2] + w4.w * fr[4 * rv + 3];
        }
        const float e = __expf((fr[q] - m) * TAU_INV);
        s += e; a += e * u;
    }
    const float s2p = a / s;

    float fw[NW];
    for (int w = 0; w < NW; w++) fw[w] = pls[w * NP + p];
    m = fw[0];
#pragma unroll
    for (int w = 1; w < NW; w++) m = fmaxf(m, fw[w]);
    s = 0.0f; a = 0.0f;
    for (int w = 0; w < NW; w++) {
        float u = 0.0f;
#pragma unroll
        for (int v4 = 0; v4 < 20; v4++) {
            float4 w4 = *(float4*)&W2s[w * NW + 4 * v4];
            u += w4.x * fw[4 * v4] + w4.y * fw[4 * v4 + 1] +
                 w4.z * fw[4 * v4 + 2] + w4.w * fw[4 * v4 + 3];
        }
        const float e = __expf((fw[w] - m) * TAU_INV);
        s += e; a += e * u;
    }
    const float p2w = a / s;

    g_sim[b * NP + p] = 0.5f * (s2p + p2w);
}

// ---------------------------------------------------------------------------
// K4: loss = -mean_i( sim[i][i] - 0.5*(lse_row_i + lse_col_i) )
// ---------------------------------------------------------------------------
__global__ void __launch_bounds__(128) k4_loss(float* __restrict__ out) {
    extern __shared__ float sm[];
    float* sims = sm;             // 128*129 (padded)
    float* red  = sm + 128 * 129; // 128
    const int tid = threadIdx.x;
    for (int i = tid; i < BS * NP; i += 128) {
        const int r = i >> 7, c = i & 127;
        sims[r * 129 + c] = g_sim[i];
    }
    __syncthreads();
    const int i = tid;
    float m = -1e30f;
    for (int j = 0; j < 128; j++) m = fmaxf(m, sims[i * 129 + j]);
    float s = 0.0f;
    for (int j = 0; j < 128; j++) s += expf(sims[i * 129 + j] - m);
    const float lser = m + logf(s);
    m = -1e30f;
    for (int j = 0; j < 128; j++) m = fmaxf(m, sims[j * 129 + i]);
    s = 0.0f;
    for (int j = 0; j < 128; j++) s += expf(sims[j * 129 + i] - m);
    const float lsec = m + logf(s);
    red[i] = sims[i * 129 + i] - 0.5f * (lser + lsec);
    __syncthreads();
    for (int st = 64; st > 0; st >>= 1) {
        if (tid < st) red[tid] += red[tid + st];
        __syncthreads();
    }
    if (tid == 0) out[0] = -red[0] / 128.0f;
}

// ---------------------------------------------------------------------------
extern "C" void kernel_launch(void* const* d_in, const int* in_sizes, int n_in,
                              void* d_out, int out_size) {
    const float* patch = (const float*)d_in[0];  // (128, 36, 768)
    const float* word  = (const float*)d_in[1];  // (128, 80, 768)
    const float* L     = (const float*)d_in[2];  // (768, 768)
    const float* Ww    = (const float*)d_in[3];  // (80, 80)
    const float* Wp    = (const float*)d_in[4];  // (36, 36)
    const float* Ww2   = (const float*)d_in[5];  // (80, 80)
    const float* Wp2   = (const float*)d_in[6];  // (36, 36)
    float* out = (float*)d_out;

    const int smem_k2 = 35952 * 4;
    const int smem_k3 = 22544 * 4;
    const int smem_k4 = (128 * 129 + 128) * 4;
    cudaFuncSetAttribute(k2_fine,   cudaFuncAttributeMaxDynamicSharedMemorySize, smem_k2);
    cudaFuncSetAttribute(k3_stage2, cudaFuncAttributeMaxDynamicSharedMemorySize, smem_k3);
    cudaFuncSetAttribute(k4_loss,   cudaFuncAttributeMaxDynamicSharedMemorySize, smem_k4);

    k1_plgemm<<<dim3(6, 72), 256>>>(patch, L);
    k2_fine<<<dim3(NP / PT, BS), 320, smem_k2>>>(word, Ww, Wp);
    k3_stage2<<<BS, 128, smem_k3>>>(Ww2, Wp2);
    k4_loss<<<1, 128, smem_k4>>>(out);
}

// round 6
// speedup vs baseline: 1.5994x; 1.3732x over previous
#include <cuda_runtime.h>
#include <cuda_bf16.h>
#include <math.h>
#include <stdint.h>

// Problem constants
#define BS   128
#define NW   80
#define NP   128
#define NQ   36
#define DIM  768
#define TAU_INV 100.0f

#define PT   4            // patches per K2 block
#define NT   144          // PT*NQ columns per tile
#define FS   148          // F row stride in smem

// Scratch (device globals: no allocation allowed)
__device__ float g_pl [NP*NQ*DIM];    // 4608 x 768  : patch @ L^T
__device__ float g_wl [BS*NP*NQ];     // word_level [b][p][q]
__device__ float g_plv[BS*NW*NP];     // patch_level [b][w][p]
__device__ float g_sim[BS*NP];        // sim [b][p]

// ---------------------------------------------------------------------------
// bf16 split helpers
// ---------------------------------------------------------------------------
__device__ __forceinline__ uint32_t pack_bf16(float lo_elem, float hi_elem) {
    // returns packed bf16x2: lo_elem in bits[0:16), hi_elem in bits[16:32)
    uint32_t r;
    asm("cvt.rn.bf16x2.f32 %0, %1, %2;" : "=r"(r) : "f"(hi_elem), "f"(lo_elem));
    return r;
}
// split float4 (4 consecutive k) into two packed-hi and two packed-lo words
__device__ __forceinline__ void split4_bf16(float4 v, uint32_t* hp, uint32_t* lp) {
    float h0 = __bfloat162float(__float2bfloat16_rn(v.x));
    float h1 = __bfloat162float(__float2bfloat16_rn(v.y));
    float h2 = __bfloat162float(__float2bfloat16_rn(v.z));
    float h3 = __bfloat162float(__float2bfloat16_rn(v.w));
    hp[0] = pack_bf16(h0, h1);
    hp[1] = pack_bf16(h2, h3);
    lp[0] = pack_bf16(v.x - h0, v.y - h1);
    lp[1] = pack_bf16(v.z - h2, v.w - h3);
}
__device__ __forceinline__ void mma_bf16(float4& d,
    uint32_t a0, uint32_t a1, uint32_t a2, uint32_t a3,
    uint32_t b0, uint32_t b1) {
    asm volatile(
        "mma.sync.aligned.m16n8k16.row.col.f32.bf16.bf16.f32 "
        "{%0,%1,%2,%3}, {%4,%5,%6,%7}, {%8,%9}, {%0,%1,%2,%3};\n"
        : "+f"(d.x), "+f"(d.y), "+f"(d.z), "+f"(d.w)
        : "r"(a0), "r"(a1), "r"(a2), "r"(a3), "r"(b0), "r"(b1));
}

// ---------------------------------------------------------------------------
// K1: pl[i][d] = sum_e patch2d[i][e] * L[d][e]    (M=4608, N=768, K=768)
// ---------------------------------------------------------------------------
#define K1_AS 20
__global__ void __launch_bounds__(256) k1_plgemm(const float* __restrict__ patch,
                                                 const float* __restrict__ L) {
    __shared__ float As[64 * K1_AS];
    __shared__ float Bs[128 * K1_AS];
    const int tid = threadIdx.x;
    const int tx = tid & 15, ty = tid >> 4;
    const int m0 = blockIdx.y * 64;
    const int n0 = blockIdx.x * 128;
    const float* Ap = patch + (size_t)m0 * DIM;
    const float* Bp = L + (size_t)n0 * DIM;

    const int ar = tid >> 2;          // 0..63
    const int ac = (tid & 3) << 2;    // 0,4,8,12

    float4 pa, pb0, pb1;
    pa  = *(const float4*)&Ap[ar * DIM + ac];
    pb0 = *(const float4*)&Bp[ar * DIM + ac];
    pb1 = *(const float4*)&Bp[(ar + 64) * DIM + ac];

    float acc[4][8];
#pragma unroll
    for (int i = 0; i < 4; i++)
#pragma unroll
        for (int j = 0; j < 8; j++) acc[i][j] = 0.0f;

    for (int kc = 0; kc < DIM / 16; kc++) {
        __syncthreads();
        *(float4*)&As[ar * K1_AS + ac] = pa;
        *(float4*)&Bs[ar * K1_AS + ac] = pb0;
        *(float4*)&Bs[(ar + 64) * K1_AS + ac] = pb1;
        __syncthreads();
        if (kc < DIM / 16 - 1) {
            const int kn = (kc + 1) * 16 + ac;
            pa  = *(const float4*)&Ap[ar * DIM + kn];
            pb0 = *(const float4*)&Bp[ar * DIM + kn];
            pb1 = *(const float4*)&Bp[(ar + 64) * DIM + kn];
        }
#pragma unroll
        for (int k4 = 0; k4 < 4; k4++) {
            float4 a4[4], b4[8];
#pragma unroll
            for (int i = 0; i < 4; i++) a4[i] = *(float4*)&As[(ty + 16 * i) * K1_AS + 4 * k4];
#pragma unroll
            for (int j = 0; j < 8; j++) b4[j] = *(float4*)&Bs[(tx + 16 * j) * K1_AS + 4 * k4];
#pragma unroll
            for (int i = 0; i < 4; i++)
#pragma unroll
                for (int j = 0; j < 8; j++)
                    acc[i][j] += a4[i].x * b4[j].x + a4[i].y * b4[j].y +
                                 a4[i].z * b4[j].z + a4[i].w * b4[j].w;
        }
    }
#pragma unroll
    for (int i = 0; i < 4; i++)
#pragma unroll
        for (int j = 0; j < 8; j++)
            g_pl[(size_t)(m0 + ty + 16 * i) * DIM + n0 + tx + 16 * j] = acc[i][j];
}

// ---------------------------------------------------------------------------
// K2 v4: bf16 2-split (hh + hl + lh) via mma.sync.m16n8k16, fused epilogue.
//   F[80][144] = word[b] @ pl[ptile]^T   (M=80, N=144, K=768)
// 320 threads = 10 warps; warp (ms,ns): rows [16ms,16ms+16), cols [72ns,72ns+72)
//
// Staging (uint32 words, packed bf16x2 pairs along k, row stride 20 words):
//   per buffer: Ah[80*20=1600] Al[1600] Bh[144*20=2880] Bl[2880] = 8960 words
//   buf0 @0, buf1 @8960  (17920 words = 71680 B)
// Epilogue aliases (after mainloop): Fs@0 (11840), SC@11840, Wws@23680,
//   Wps@30080, cmax@31376, csum@31520 -> 31664 floats = 126656 B total.
// ---------------------------------------------------------------------------
#define SMW_BUF 8960
#define PRS 20          // pair-row stride in words (16 pairs + 4 pad, bank-perfect)

__global__ void __launch_bounds__(320) k2_fine(const float* __restrict__ word,
                                               const float* __restrict__ Ww,
                                               const float* __restrict__ Wp) {
    extern __shared__ float sm[];
    uint32_t* smw = (uint32_t*)sm;
    float* Fs   = sm;            // 11840
    float* SC   = sm + 11840;    // 11840
    float* Wws  = sm + 23680;    // 6400
    float* Wps  = sm + 30080;    // 1296
    float* cmax = sm + 31376;    // 144
    float* csum = sm + 31520;    // 144

    const int tid  = threadIdx.x;
    const int lane = tid & 31, wid = tid >> 5;
    const int g  = lane >> 2, t4 = lane & 3;
    const int ms = wid >> 1,  ns = wid & 1;        // wid 0..9
    const int b = blockIdx.y, pb = blockIdx.x;

    // stage small weight matrices (region beyond both buffers: words >= 23680)
    for (int i = tid; i < 1600; i += 320) ((float4*)Wws)[i] = ((const float4*)Ww)[i];
    for (int i = tid; i < 324;  i += 320) ((float4*)Wps)[i] = ((const float4*)Wp)[i];

    const float* Aw = word + (size_t)b * NW * DIM;
    const float* Bp = g_pl + (size_t)pb * NT * DIM;   // 144 contiguous rows

    // --- prefetch chunk 0 (fp32) ---
    float4 pa[2], pb4[4];
#pragma unroll
    for (int j = 0; j < 2; j++) {
        const int pos = tid + 320 * j;                 // < 640
        pa[j] = *(const float4*)&Aw[(pos >> 3) * DIM + 4 * (pos & 7)];
    }
#pragma unroll
    for (int j = 0; j < 4; j++) {
        const int pos = tid + 320 * j;
        if (pos < 1152)
            pb4[j] = *(const float4*)&Bp[(pos >> 3) * DIM + 4 * (pos & 7)];
    }

    float4 acc[9];
#pragma unroll
    for (int j = 0; j < 9; j++) acc[j] = make_float4(0.f, 0.f, 0.f, 0.f);

    for (int kc = 0; kc < 24; kc++) {
        __syncthreads();
        uint32_t* Ah = smw + (kc & 1) * SMW_BUF;
        uint32_t* Al = Ah + 1600;
        uint32_t* Bh = Ah + 3200;
        uint32_t* Bl = Ah + 6080;
        // split + store stage (packed bf16 pairs)
#pragma unroll
        for (int j = 0; j < 2; j++) {
            const int pos = tid + 320 * j, r = pos >> 3, c4 = pos & 7;
            uint32_t hp[2], lp[2];
            split4_bf16(pa[j], hp, lp);
            *(uint2*)&Ah[r * PRS + 2 * c4] = make_uint2(hp[0], hp[1]);
            *(uint2*)&Al[r * PRS + 2 * c4] = make_uint2(lp[0], lp[1]);
        }
#pragma unroll
        for (int j = 0; j < 4; j++) {
            const int pos = tid + 320 * j;
            if (pos < 1152) {
                const int r = pos >> 3, c4 = pos & 7;
                uint32_t hp[2], lp[2];
                split4_bf16(pb4[j], hp, lp);
                *(uint2*)&Bh[r * PRS + 2 * c4] = make_uint2(hp[0], hp[1]);
                *(uint2*)&Bl[r * PRS + 2 * c4] = make_uint2(lp[0], lp[1]);
            }
        }
        __syncthreads();
        // prefetch next chunk
        if (kc < 23) {
            const int kn = (kc + 1) * 32;
#pragma unroll
            for (int j = 0; j < 2; j++) {
                const int pos = tid + 320 * j;
                pa[j] = *(const float4*)&Aw[(pos >> 3) * DIM + kn + 4 * (pos & 7)];
            }
#pragma unroll
            for (int j = 0; j < 4; j++) {
                const int pos = tid + 320 * j;
                if (pos < 1152)
                    pb4[j] = *(const float4*)&Bp[(pos >> 3) * DIM + kn + 4 * (pos & 7)];
            }
        }
        // compute: 2 k16-steps per chunk
#pragma unroll
        for (int ks = 0; ks < 2; ks++) {
            const int arow = (16 * ms + g) * PRS + ks * 8 + t4;
            const uint32_t ah0 = Ah[arow];
            const uint32_t ah1 = Ah[arow + 8 * PRS];
            const uint32_t ah2 = Ah[arow + 4];
            const uint32_t ah3 = Ah[arow + 8 * PRS + 4];
            const uint32_t al0 = Al[arow];
            const uint32_t al1 = Al[arow + 8 * PRS];
            const uint32_t al2 = Al[arow + 4];
            const uint32_t al3 = Al[arow + 8 * PRS + 4];
#pragma unroll
            for (int nt = 0; nt < 9; nt++) {
                const int brow = (72 * ns + 8 * nt + g) * PRS + ks * 8 + t4;
                const uint32_t bh0 = Bh[brow];
                const uint32_t bh1 = Bh[brow + 4];
                const uint32_t bl0 = Bl[brow];
                const uint32_t bl1 = Bl[brow + 4];
                mma_bf16(acc[nt], ah0, ah1, ah2, ah3, bh0, bh1);
                mma_bf16(acc[nt], ah0, ah1, ah2, ah3, bl0, bl1);
                mma_bf16(acc[nt], al0, al1, al2, al3, bh0, bh1);
            }
        }
    }
    __syncthreads();   // staging buffers dead; about to write Fs over them

    // F tile -> smem (C fragment layout: rows g/g+8, cols 2t4, 2t4+1)
#pragma unroll
    for (int nt = 0; nt < 9; nt++) {
        const int row = 16 * ms + g, col = 72 * ns + 8 * nt + 2 * t4;
        Fs[row * FS + col]           = acc[nt].x;
        Fs[row * FS + col + 1]       = acc[nt].y;
        Fs[(row + 8) * FS + col]     = acc[nt].z;
        Fs[(row + 8) * FS + col + 1] = acc[nt].w;
    }
    __syncthreads();

    // column softmax stats (over w)
    if (tid < NT) {
        float m = -1e30f;
        for (int w = 0; w < NW; w++) m = fmaxf(m, Fs[w * FS + tid]);
        float s = 0.0f;
        for (int w = 0; w < NW; w++) s += __expf((Fs[w * FS + tid] - m) * TAU_INV);
        cmax[tid] = m;
        csum[tid] = s;
    }

    // G = Ww @ F  (80x80 * 80x144) on first 256 threads, into SC
    float ga[5][9];
    if (tid < 256) {
        const int tx = tid & 15, ty = tid >> 4;
#pragma unroll
        for (int i = 0; i < 5; i++)
#pragma unroll
            for (int j = 0; j < 9; j++) ga[i][j] = 0.0f;
        for (int v4 = 0; v4 < 20; v4++) {
            float aa[5][4];
#pragma unroll
            for (int i = 0; i < 5; i++) {
                float4 a4 = *(float4*)&Wws[(ty + 16 * i) * 80 + 4 * v4];
                aa[i][0] = a4.x; aa[i][1] = a4.y; aa[i][2] = a4.z; aa[i][3] = a4.w;
            }
#pragma unroll
            for (int vv = 0; vv < 4; vv++) {
                const int v = 4 * v4 + vv;
                float bv[9];
#pragma unroll
                for (int j = 0; j < 9; j++) bv[j] = Fs[v * FS + tx + 16 * j];
#pragma unroll
                for (int i = 0; i < 5; i++)
#pragma unroll
                    for (int j = 0; j < 9; j++) ga[i][j] += aa[i][vv] * bv[j];
            }
        }
    }
    __syncthreads();   // cmax/csum published; Fs reads for G done
    if (tid < 256) {
        const int tx = tid & 15, ty = tid >> 4;
#pragma unroll
        for (int i = 0; i < 5; i++)
#pragma unroll
            for (int j = 0; j < 9; j++)
                SC[(ty + 16 * i) * FS + tx + 16 * j] = ga[i][j];
    }
    __syncthreads();

    // word_level[b, pb*4 + j/36, j%36]
    if (tid < NT) {
        const float m = cmax[tid];
        const float s = csum[tid];
        float a = 0.0f;
        for (int w = 0; w < NW; w++)
            a += __expf((Fs[w * FS + tid] - m) * TAU_INV) * SC[w * FS + tid];
        g_wl[(size_t)b * (NP * NQ) + pb * NT + tid] = a / s;
    }

    // patch_level[b, w, pb*4 + p]  (NW*PT = 320: one row per thread)
    for (int pr = tid; pr < NW * PT; pr += 320) {
        const int w = pr >> 2, p = pr & 3;
        const float* frow = &Fs[w * FS + p * NQ];
        float fr[NQ];
#pragma unroll
        for (int c = 0; c < 9; c++) *(float4*)&fr[4 * c] = *(const float4*)&frow[4 * c];
        float m = fr[0];
#pragma unroll
        for (int q = 1; q < NQ; q++) m = fmaxf(m, fr[q]);
        float s = 0.0f, a = 0.0f;
        for (int q = 0; q < NQ; q++) {
            float u = 0.0f;
#pragma unroll
            for (int rv = 0; rv < 9; rv++) {
                float4 w4 = *(float4*)&Wps[q * NQ + 4 * rv];
                u += w4.x * fr[4 * rv] + w4.y * fr[4 * rv + 1] +
                     w4.z * fr[4 * rv + 2] + w4.w * fr[4 * rv + 3];
            }
            const float e = __expf((fr[q] - m) * TAU_INV);
            s += e;
            a += e * u;
        }
        g_plv[(size_t)b * (NW * NP) + w * NP + pb * PT + p] = a / s;
    }
}

// ---------------------------------------------------------------------------
// K3: per b: s2p/p2w second-level reductions -> sim[b][p]
// ---------------------------------------------------------------------------
__global__ void __launch_bounds__(128) k3_stage2(const float* __restrict__ Ww2,
                                                 const float* __restrict__ Wp2) {
    extern __shared__ float sm[];
    float* wls = sm;            // 4608
    float* pls = sm + 4608;     // 10240
    float* W2s = sm + 14848;    // 6400
    float* P2s = sm + 21248;    // 1296
    const int b = blockIdx.x, tid = threadIdx.x;

    const float4* s1 = (const float4*)(g_wl + (size_t)b * (NP * NQ));
    for (int i = tid; i < 1152; i += 128) ((float4*)wls)[i] = s1[i];
    const float4* s2 = (const float4*)(g_plv + (size_t)b * (NW * NP));
    for (int i = tid; i < 2560; i += 128) ((float4*)pls)[i] = s2[i];
    for (int i = tid; i < 1600; i += 128) ((float4*)W2s)[i] = ((const float4*)Ww2)[i];
    for (int i = tid; i < 324;  i += 128) ((float4*)P2s)[i] = ((const float4*)Wp2)[i];
    __syncthreads();

    const int p = tid;
    float fr[NQ];
#pragma unroll
    for (int c = 0; c < 9; c++) *(float4*)&fr[4 * c] = *(float4*)&wls[p * NQ + 4 * c];
    float m = fr[0];
#pragma unroll
    for (int q = 1; q < NQ; q++) m = fmaxf(m, fr[q]);
    float s = 0.0f, a = 0.0f;
    for (int q = 0; q < NQ; q++) {
        float u = 0.0f;
#pragma unroll
        for (int rv = 0; rv < 9; rv++) {
            float4 w4 = *(float4*)&P2s[q * NQ + 4 * rv];
            u += w4.x * fr[4 * rv] + w4.y * fr[4 * rv + 1] +
                 w4.z * fr[4 * rv + 2] + w4.w * fr[4 * rv + 3];
        }
        const float e = __expf((fr[q] - m) * TAU_INV);
        s += e; a += e * u;
    }
    const float s2p = a / s;

    float fw[NW];
    for (int w = 0; w < NW; w++) fw[w] = pls[w * NP + p];
    m = fw[0];
#pragma unroll
    for (int w = 1; w < NW; w++) m = fmaxf(m, fw[w]);
    s = 0.0f; a = 0.0f;
    for (int w = 0; w < NW; w++) {
        float u = 0.0f;
#pragma unroll
        for (int v4 = 0; v4 < 20; v4++) {
            float4 w4 = *(float4*)&W2s[w * NW + 4 * v4];
            u += w4.x * fw[4 * v4] + w4.y * fw[4 * v4 + 1] +
                 w4.z * fw[4 * v4 + 2] + w4.w * fw[4 * v4 + 3];
        }
        const float e = __expf((fw[w] - m) * TAU_INV);
        s += e; a += e * u;
    }
    const float p2w = a / s;

    g_sim[b * NP + p] = 0.5f * (s2p + p2w);
}

// ---------------------------------------------------------------------------
// K4: loss = -mean_i( sim[i][i] - 0.5*(lse_row_i + lse_col_i) )
// ---------------------------------------------------------------------------
__global__ void __launch_bounds__(128) k4_loss(float* __restrict__ out) {
    extern __shared__ float sm[];
    float* sims = sm;             // 128*129 (padded)
    float* red  = sm + 128 * 129; // 128
    const int tid = threadIdx.x;
    for (int i = tid; i < BS * NP; i += 128) {
        const int r = i >> 7, c = i & 127;
        sims[r * 129 + c] = g_sim[i];
    }
    __syncthreads();
    const int i = tid;
    float m = -1e30f;
    for (int j = 0; j < 128; j++) m = fmaxf(m, sims[i * 129 + j]);
    float s = 0.0f;
    for (int j = 0; j < 128; j++) s += expf(sims[i * 129 + j] - m);
    const float lser = m + logf(s);
    m = -1e30f;
    for (int j = 0; j < 128; j++) m = fmaxf(m, sims[j * 129 + i]);
    s = 0.0f;
    for (int j = 0; j < 128; j++) s += expf(sims[j * 129 + i] - m);
    const float lsec = m + logf(s);
    red[i] = sims[i * 129 + i] - 0.5f * (lser + lsec);
    __syncthreads();
    for (int st = 64; st > 0; st >>= 1) {
        if (tid < st) red[tid] += red[tid + st];
        __syncthreads();
    }
    if (tid == 0) out[0] = -red[0] / 128.0f;
}

// ---------------------------------------------------------------------------
extern "C" void kernel_launch(void* const* d_in, const int* in_sizes, int n_in,
                              void* d_out, int out_size) {
    const float* patch = (const float*)d_in[0];  // (128, 36, 768)
    const float* word  = (const float*)d_in[1];  // (128, 80, 768)
    const float* L     = (const float*)d_in[2];  // (768, 768)
    const float* Ww    = (const float*)d_in[3];  // (80, 80)
    const float* Wp    = (const float*)d_in[4];  // (36, 36)
    const float* Ww2   = (const float*)d_in[5];  // (80, 80)
    const float* Wp2   = (const float*)d_in[6];  // (36, 36)
    float* out = (float*)d_out;

    const int smem_k2 = 31664 * 4;
    const int smem_k3 = 22544 * 4;
    const int smem_k4 = (128 * 129 + 128) * 4;
    cudaFuncSetAttribute(k2_fine,   cudaFuncAttributeMaxDynamicSharedMemorySize, smem_k2);
    cudaFuncSetAttribute(k3_stage2, cudaFuncAttributeMaxDynamicSharedMemorySize, smem_k3);
    cudaFuncSetAttribute(k4_loss,   cudaFuncAttributeMaxDynamicSharedMemorySize, smem_k4);

    k1_plgemm<<<dim3(6, 72), 256>>>(patch, L);
    k2_fine<<<dim3(NP / PT, BS), 320, smem_k2>>>(word, Ww, Wp);
    k3_stage2<<<BS, 128, smem_k3>>>(Ww2, Wp2);
    k4_loss<<<1, 128, smem_k4>>>(out);
}

// round 7
// speedup vs baseline: 1.8871x; 1.1799x over previous
#include <cuda_runtime.h>
#include <cuda_bf16.h>
#include <math.h>
#include <stdint.h>

// Problem constants
#define BS   128
#define NW   80
#define NP   128
#define NQ   36
#define DIM  768
#define TAU_INV 100.0f

#define PT   4            // patches per K2 block
#define NT   144          // PT*NQ columns per tile
#define FS   148          // F row stride in smem

// Scratch (device globals: no allocation allowed)
__device__ float g_pl [NP*NQ*DIM];    // 4608 x 768  : patch @ L^T
__device__ float g_wl [BS*NP*NQ];     // word_level [b][p][q]
__device__ float g_plv[BS*NW*NP];     // patch_level [b][w][p]
__device__ float g_sim[BS*NP];        // sim [b][p]

// ---------------------------------------------------------------------------
// bf16 split helpers
// ---------------------------------------------------------------------------
__device__ __forceinline__ uint32_t pack_bf16(float lo_elem, float hi_elem) {
    uint32_t r;
    asm("cvt.rn.bf16x2.f32 %0, %1, %2;" : "=r"(r) : "f"(hi_elem), "f"(lo_elem));
    return r;
}
__device__ __forceinline__ void split4_bf16(float4 v, uint32_t* hp, uint32_t* lp) {
    float h0 = __bfloat162float(__float2bfloat16_rn(v.x));
    float h1 = __bfloat162float(__float2bfloat16_rn(v.y));
    float h2 = __bfloat162float(__float2bfloat16_rn(v.z));
    float h3 = __bfloat162float(__float2bfloat16_rn(v.w));
    hp[0] = pack_bf16(h0, h1);
    hp[1] = pack_bf16(h2, h3);
    lp[0] = pack_bf16(v.x - h0, v.y - h1);
    lp[1] = pack_bf16(v.z - h2, v.w - h3);
}
__device__ __forceinline__ void mma_bf16(float4& d,
    uint32_t a0, uint32_t a1, uint32_t a2, uint32_t a3,
    uint32_t b0, uint32_t b1) {
    asm volatile(
        "mma.sync.aligned.m16n8k16.row.col.f32.bf16.bf16.f32 "
        "{%0,%1,%2,%3}, {%4,%5,%6,%7}, {%8,%9}, {%0,%1,%2,%3};\n"
        : "+f"(d.x), "+f"(d.y), "+f"(d.z), "+f"(d.w)
        : "r"(a0), "r"(a1), "r"(a2), "r"(a3), "r"(b0), "r"(b1));
}

// ---------------------------------------------------------------------------
// K1: pl[i][d] = sum_e patch2d[i][e] * L[d][e]    (M=4608, N=768, K=768)
// ---------------------------------------------------------------------------
#define K1_AS 20
__global__ void __launch_bounds__(256) k1_plgemm(const float* __restrict__ patch,
                                                 const float* __restrict__ L) {
    __shared__ float As[64 * K1_AS];
    __shared__ float Bs[128 * K1_AS];
    const int tid = threadIdx.x;
    const int tx = tid & 15, ty = tid >> 4;
    const int m0 = blockIdx.y * 64;
    const int n0 = blockIdx.x * 128;
    const float* Ap = patch + (size_t)m0 * DIM;
    const float* Bp = L + (size_t)n0 * DIM;

    const int ar = tid >> 2;          // 0..63
    const int ac = (tid & 3) << 2;    // 0,4,8,12

    float4 pa, pb0, pb1;
    pa  = *(const float4*)&Ap[ar * DIM + ac];
    pb0 = *(const float4*)&Bp[ar * DIM + ac];
    pb1 = *(const float4*)&Bp[(ar + 64) * DIM + ac];

    float acc[4][8];
#pragma unroll
    for (int i = 0; i < 4; i++)
#pragma unroll
        for (int j = 0; j < 8; j++) acc[i][j] = 0.0f;

    for (int kc = 0; kc < DIM / 16; kc++) {
        __syncthreads();
        *(float4*)&As[ar * K1_AS + ac] = pa;
        *(float4*)&Bs[ar * K1_AS + ac] = pb0;
        *(float4*)&Bs[(ar + 64) * K1_AS + ac] = pb1;
        __syncthreads();
        if (kc < DIM / 16 - 1) {
            const int kn = (kc + 1) * 16 + ac;
            pa  = *(const float4*)&Ap[ar * DIM + kn];
            pb0 = *(const float4*)&Bp[ar * DIM + kn];
            pb1 = *(const float4*)&Bp[(ar + 64) * DIM + kn];
        }
#pragma unroll
        for (int k4 = 0; k4 < 4; k4++) {
            float4 a4[4], b4[8];
#pragma unroll
            for (int i = 0; i < 4; i++) a4[i] = *(float4*)&As[(ty + 16 * i) * K1_AS + 4 * k4];
#pragma unroll
            for (int j = 0; j < 8; j++) b4[j] = *(float4*)&Bs[(tx + 16 * j) * K1_AS + 4 * k4];
#pragma unroll
            for (int i = 0; i < 4; i++)
#pragma unroll
                for (int j = 0; j < 8; j++)
                    acc[i][j] += a4[i].x * b4[j].x + a4[i].y * b4[j].y +
                                 a4[i].z * b4[j].z + a4[i].w * b4[j].w;
        }
    }
#pragma unroll
    for (int i = 0; i < 4; i++)
#pragma unroll
        for (int j = 0; j < 8; j++)
            g_pl[(size_t)(m0 + ty + 16 * i) * DIM + n0 + tx + 16 * j] = acc[i][j];
}

// ---------------------------------------------------------------------------
// K2 v5: bf16 2-split mma.sync mainloop + register-G epilogue, 2 CTAs/SM.
//   F[80][144] = word[b] @ pl[ptile]^T   (M=80, N=144, K=768)
// smem (floats/words):
//   mainloop buffers: buf0 @0 (8960 w), buf1 @8960 (8960 w)  -> 0..17920
//   epilogue aliases: Fs@0 (80*148=11840), red@11840 (16*148=2368)
//   weights (disjoint from buffers): Wws@17920 (6400), Wps@24320 (1296),
//   cmax@25616 (144), csum@25760 (144)  -> total 25904 floats = 103616 B
// ---------------------------------------------------------------------------
#define SMW_BUF 8960
#define PRS 20          // pair-row stride in words

__global__ void __launch_bounds__(320, 2) k2_fine(const float* __restrict__ word,
                                                  const float* __restrict__ Ww,
                                                  const float* __restrict__ Wp) {
    extern __shared__ float sm[];
    uint32_t* smw = (uint32_t*)sm;
    float* Fs   = sm;            // 11840
    float* red  = sm + 11840;    // 2368
    float* Wws  = sm + 17920;    // 6400
    float* Wps  = sm + 24320;    // 1296
    float* cmax = sm + 25616;    // 144
    float* csum = sm + 25760;    // 144

    const int tid  = threadIdx.x;
    const int lane = tid & 31, wid = tid >> 5;
    const int g  = lane >> 2, t4 = lane & 3;
    const int ms = wid >> 1,  ns = wid & 1;        // wid 0..9
    const int b = blockIdx.y, pb = blockIdx.x;

    // stage small weight matrices (region disjoint from mainloop buffers)
    for (int i = tid; i < 1600; i += 320) ((float4*)Wws)[i] = ((const float4*)Ww)[i];
    for (int i = tid; i < 324;  i += 320) ((float4*)Wps)[i] = ((const float4*)Wp)[i];

    const float* Aw = word + (size_t)b * NW * DIM;
    const float* Bp = g_pl + (size_t)pb * NT * DIM;   // 144 contiguous rows

    // --- prefetch chunk 0 (fp32) ---
    float4 pa[2], pb4[4];
#pragma unroll
    for (int j = 0; j < 2; j++) {
        const int pos = tid + 320 * j;                 // < 640
        pa[j] = *(const float4*)&Aw[(pos >> 3) * DIM + 4 * (pos & 7)];
    }
#pragma unroll
    for (int j = 0; j < 4; j++) {
        const int pos = tid + 320 * j;
        if (pos < 1152)
            pb4[j] = *(const float4*)&Bp[(pos >> 3) * DIM + 4 * (pos & 7)];
    }

    float4 acc[9];
#pragma unroll
    for (int j = 0; j < 9; j++) acc[j] = make_float4(0.f, 0.f, 0.f, 0.f);

    for (int kc = 0; kc < 24; kc++) {
        __syncthreads();
        uint32_t* Ah = smw + (kc & 1) * SMW_BUF;
        uint32_t* Al = Ah + 1600;
        uint32_t* Bh = Ah + 3200;
        uint32_t* Bl = Ah + 6080;
#pragma unroll
        for (int j = 0; j < 2; j++) {
            const int pos = tid + 320 * j, r = pos >> 3, c4 = pos & 7;
            uint32_t hp[2], lp[2];
            split4_bf16(pa[j], hp, lp);
            *(uint2*)&Ah[r * PRS + 2 * c4] = make_uint2(hp[0], hp[1]);
            *(uint2*)&Al[r * PRS + 2 * c4] = make_uint2(lp[0], lp[1]);
        }
#pragma unroll
        for (int j = 0; j < 4; j++) {
            const int pos = tid + 320 * j;
            if (pos < 1152) {
                const int r = pos >> 3, c4 = pos & 7;
                uint32_t hp[2], lp[2];
                split4_bf16(pb4[j], hp, lp);
                *(uint2*)&Bh[r * PRS + 2 * c4] = make_uint2(hp[0], hp[1]);
                *(uint2*)&Bl[r * PRS + 2 * c4] = make_uint2(lp[0], lp[1]);
            }
        }
        __syncthreads();
        if (kc < 23) {
            const int kn = (kc + 1) * 32;
#pragma unroll
            for (int j = 0; j < 2; j++) {
                const int pos = tid + 320 * j;
                pa[j] = *(const float4*)&Aw[(pos >> 3) * DIM + kn + 4 * (pos & 7)];
            }
#pragma unroll
            for (int j = 0; j < 4; j++) {
                const int pos = tid + 320 * j;
                if (pos < 1152)
                    pb4[j] = *(const float4*)&Bp[(pos >> 3) * DIM + kn + 4 * (pos & 7)];
            }
        }
#pragma unroll
        for (int ks = 0; ks < 2; ks++) {
            const int arow = (16 * ms + g) * PRS + ks * 8 + t4;
            const uint32_t ah0 = Ah[arow];
            const uint32_t ah1 = Ah[arow + 8 * PRS];
            const uint32_t ah2 = Ah[arow + 4];
            const uint32_t ah3 = Ah[arow + 8 * PRS + 4];
            const uint32_t al0 = Al[arow];
            const uint32_t al1 = Al[arow + 8 * PRS];
            const uint32_t al2 = Al[arow + 4];
            const uint32_t al3 = Al[arow + 8 * PRS + 4];
#pragma unroll
            for (int nt = 0; nt < 9; nt++) {
                const int brow = (72 * ns + 8 * nt + g) * PRS + ks * 8 + t4;
                const uint32_t bh0 = Bh[brow];
                const uint32_t bh1 = Bh[brow + 4];
                const uint32_t bl0 = Bl[brow];
                const uint32_t bl1 = Bl[brow + 4];
                mma_bf16(acc[nt], ah0, ah1, ah2, ah3, bh0, bh1);
                mma_bf16(acc[nt], ah0, ah1, ah2, ah3, bl0, bl1);
                mma_bf16(acc[nt], al0, al1, al2, al3, bh0, bh1);
            }
        }
    }
    __syncthreads();   // staging buffers dead; about to write Fs over them

    // F tile -> smem (C fragment layout: rows g/g+8, cols 2t4, 2t4+1)
#pragma unroll
    for (int nt = 0; nt < 9; nt++) {
        const int row = 16 * ms + g, col = 72 * ns + 8 * nt + 2 * t4;
        Fs[row * FS + col]           = acc[nt].x;
        Fs[row * FS + col + 1]       = acc[nt].y;
        Fs[(row + 8) * FS + col]     = acc[nt].z;
        Fs[(row + 8) * FS + col + 1] = acc[nt].w;
    }
    __syncthreads();

    // phase A: column softmax stats (tid<144) + G = Ww@F in registers (tid<256)
    if (tid < NT) {
        float m = -1e30f;
        for (int w = 0; w < NW; w++) m = fmaxf(m, Fs[w * FS + tid]);
        float s = 0.0f;
        for (int w = 0; w < NW; w++) s += __expf((Fs[w * FS + tid] - m) * TAU_INV);
        cmax[tid] = m;
        csum[tid] = s;
    }
    float ga[5][9];
    if (tid < 256) {
        const int tx = tid & 15, ty = tid >> 4;
#pragma unroll
        for (int i = 0; i < 5; i++)
#pragma unroll
            for (int j = 0; j < 9; j++) ga[i][j] = 0.0f;
        for (int v4 = 0; v4 < 20; v4++) {
            float aa[5][4];
#pragma unroll
            for (int i = 0; i < 5; i++) {
                float4 a4 = *(float4*)&Wws[(ty + 16 * i) * 80 + 4 * v4];
                aa[i][0] = a4.x; aa[i][1] = a4.y; aa[i][2] = a4.z; aa[i][3] = a4.w;
            }
#pragma unroll
            for (int vv = 0; vv < 4; vv++) {
                const int v = 4 * v4 + vv;
                float bv[9];
#pragma unroll
                for (int j = 0; j < 9; j++) bv[j] = Fs[v * FS + tx + 16 * j];
#pragma unroll
                for (int i = 0; i < 5; i++)
#pragma unroll
                    for (int j = 0; j < 9; j++) ga[i][j] += aa[i][vv] * bv[j];
            }
        }
    }
    __syncthreads();   // cmax/csum published

    // phase B: per-thread partial  sum_i e(F[ty+16i][c]) * ga[i][j]  -> red[ty][c]
    if (tid < 256) {
        const int tx = tid & 15, ty = tid >> 4;
#pragma unroll
        for (int j = 0; j < 9; j++) {
            const int c = tx + 16 * j;
            const float m = cmax[c];
            float part = 0.0f;
#pragma unroll
            for (int i = 0; i < 5; i++)
                part += __expf((Fs[(ty + 16 * i) * FS + c] - m) * TAU_INV) * ga[i][j];
            red[ty * FS + c] = part;
        }
    }
    __syncthreads();

    // phase C: word_level = (sum_ty red[ty][c]) / csum[c]
    if (tid < NT) {
        float a = 0.0f;
#pragma unroll
        for (int t = 0; t < 16; t++) a += red[t * FS + tid];
        g_wl[(size_t)b * (NP * NQ) + pb * NT + tid] = a / csum[tid];
    }

    // patch_level[b, w, pb*4 + p]  (NW*PT = 320: one row per thread)
    for (int pr = tid; pr < NW * PT; pr += 320) {
        const int w = pr >> 2, p = pr & 3;
        const float* frow = &Fs[w * FS + p * NQ];
        float fr[NQ];
#pragma unroll
        for (int c = 0; c < 9; c++) *(float4*)&fr[4 * c] = *(const float4*)&frow[4 * c];
        float m = fr[0];
#pragma unroll
        for (int q = 1; q < NQ; q++) m = fmaxf(m, fr[q]);
        float s = 0.0f, a = 0.0f;
        for (int q = 0; q < NQ; q++) {
            float u = 0.0f;
#pragma unroll
            for (int rv = 0; rv < 9; rv++) {
                float4 w4 = *(float4*)&Wps[q * NQ + 4 * rv];
                u += w4.x * fr[4 * rv] + w4.y * fr[4 * rv + 1] +
                     w4.z * fr[4 * rv + 2] + w4.w * fr[4 * rv + 3];
            }
            const float e = __expf((fr[q] - m) * TAU_INV);
            s += e;
            a += e * u;
        }
        g_plv[(size_t)b * (NW * NP) + w * NP + pb * PT + p] = a / s;
    }
}

// ---------------------------------------------------------------------------
// K3: per b: s2p/p2w second-level reductions -> sim[b][p]
// ---------------------------------------------------------------------------
__global__ void __launch_bounds__(128) k3_stage2(const float* __restrict__ Ww2,
                                                 const float* __restrict__ Wp2) {
    extern __shared__ float sm[];
    float* wls = sm;            // 4608
    float* pls = sm + 4608;     // 10240
    float* W2s = sm + 14848;    // 6400
    float* P2s = sm + 21248;    // 1296
    const int b = blockIdx.x, tid = threadIdx.x;

    const float4* s1 = (const float4*)(g_wl + (size_t)b * (NP * NQ));
    for (int i = tid; i < 1152; i += 128) ((float4*)wls)[i] = s1[i];
    const float4* s2 = (const float4*)(g_plv + (size_t)b * (NW * NP));
    for (int i = tid; i < 2560; i += 128) ((float4*)pls)[i] = s2[i];
    for (int i = tid; i < 1600; i += 128) ((float4*)W2s)[i] = ((const float4*)Ww2)[i];
    for (int i = tid; i < 324;  i += 128) ((float4*)P2s)[i] = ((const float4*)Wp2)[i];
    __syncthreads();

    const int p = tid;
    float fr[NQ];
#pragma unroll
    for (int c = 0; c < 9; c++) *(float4*)&fr[4 * c] = *(float4*)&wls[p * NQ + 4 * c];
    float m = fr[0];
#pragma unroll
    for (int q = 1; q < NQ; q++) m = fmaxf(m, fr[q]);
    float s = 0.0f, a = 0.0f;
    for (int q = 0; q < NQ; q++) {
        float u = 0.0f;
#pragma unroll
        for (int rv = 0; rv < 9; rv++) {
            float4 w4 = *(float4*)&P2s[q * NQ + 4 * rv];
            u += w4.x * fr[4 * rv] + w4.y * fr[4 * rv + 1] +
                 w4.z * fr[4 * rv + 2] + w4.w * fr[4 * rv + 3];
        }
        const float e = __expf((fr[q] - m) * TAU_INV);
        s += e; a += e * u;
    }
    const float s2p = a / s;

    float fw[NW];
    for (int w = 0; w < NW; w++) fw[w] = pls[w * NP + p];
    m = fw[0];
#pragma unroll
    for (int w = 1; w < NW; w++) m = fmaxf(m, fw[w]);
    s = 0.0f; a = 0.0f;
    for (int w = 0; w < NW; w++) {
        float u = 0.0f;
#pragma unroll
        for (int v4 = 0; v4 < 20; v4++) {
            float4 w4 = *(float4*)&W2s[w * NW + 4 * v4];
            u += w4.x * fw[4 * v4] + w4.y * fw[4 * v4 + 1] +
                 w4.z * fw[4 * v4 + 2] + w4.w * fw[4 * v4 + 3];
        }
        const float e = __expf((fw[w] - m) * TAU_INV);
        s += e; a += e * u;
    }
    const float p2w = a / s;

    g_sim[b * NP + p] = 0.5f * (s2p + p2w);
}

// ---------------------------------------------------------------------------
// K4: loss = -mean_i( sim[i][i] - 0.5*(lse_row_i + lse_col_i) )
// ---------------------------------------------------------------------------
__global__ void __launch_bounds__(128) k4_loss(float* __restrict__ out) {
    extern __shared__ float sm[];
    float* sims = sm;             // 128*129 (padded)
    float* red  = sm + 128 * 129; // 128
    const int tid = threadIdx.x;
    for (int i = tid; i < BS * NP; i += 128) {
        const int r = i >> 7, c = i & 127;
        sims[r * 129 + c] = g_sim[i];
    }
    __syncthreads();
    const int i = tid;
    float m = -1e30f;
    for (int j = 0; j < 128; j++) m = fmaxf(m, sims[i * 129 + j]);
    float s = 0.0f;
    for (int j = 0; j < 128; j++) s += expf(sims[i * 129 + j] - m);
    const float lser = m + logf(s);
    m = -1e30f;
    for (int j = 0; j < 128; j++) m = fmaxf(m, sims[j * 129 + i]);
    s = 0.0f;
    for (int j = 0; j < 128; j++) s += expf(sims[j * 129 + i] - m);
    const float lsec = m + logf(s);
    red[i] = sims[i * 129 + i] - 0.5f * (lser + lsec);
    __syncthreads();
    for (int st = 64; st > 0; st >>= 1) {
        if (tid < st) red[tid] += red[tid + st];
        __syncthreads();
    }
    if (tid == 0) out[0] = -red[0] / 128.0f;
}

// ---------------------------------------------------------------------------
extern "C" void kernel_launch(void* const* d_in, const int* in_sizes, int n_in,
                              void* d_out, int out_size) {
    const float* patch = (const float*)d_in[0];  // (128, 36, 768)
    const float* word  = (const float*)d_in[1];  // (128, 80, 768)
    const float* L     = (const float*)d_in[2];  // (768, 768)
    const float* Ww    = (const float*)d_in[3];  // (80, 80)
    const float* Wp    = (const float*)d_in[4];  // (36, 36)
    const float* Ww2   = (const float*)d_in[5];  // (80, 80)
    const float* Wp2   = (const float*)d_in[6];  // (36, 36)
    float* out = (float*)d_out;

    const int smem_k2 = 25904 * 4;
    const int smem_k3 = 22544 * 4;
    const int smem_k4 = (128 * 129 + 128) * 4;
    cudaFuncSetAttribute(k2_fine,   cudaFuncAttributeMaxDynamicSharedMemorySize, smem_k2);
    cudaFuncSetAttribute(k3_stage2, cudaFuncAttributeMaxDynamicSharedMemorySize, smem_k3);
    cudaFuncSetAttribute(k4_loss,   cudaFuncAttributeMaxDynamicSharedMemorySize, smem_k4);

    k1_plgemm<<<dim3(6, 72), 256>>>(patch, L);
    k2_fine<<<dim3(NP / PT, BS), 320, smem_k2>>>(word, Ww, Wp);
    k3_stage2<<<BS, 128, smem_k3>>>(Ww2, Wp2);
    k4_loss<<<1, 128, smem_k4>>>(out);
}

// round 8
// speedup vs baseline: 2.0310x; 1.0763x over previous
#include <cuda_runtime.h>
#include <cuda_bf16.h>
#include <cuda_fp16.h>
#include <math.h>
#include <stdint.h>

// Problem constants
#define BS   128
#define NW   80
#define NP   128
#define NQ   36
#define DIM  768
#define TAU_INV 100.0f

#define PT   4            // patches per K2 block
#define NT   144          // PT*NQ columns per tile
#define FS   148          // F row stride in smem

// Scratch (device globals: no allocation allowed)
__device__ float g_pl [NP*NQ*DIM];    // 4608 x 768  : patch @ L^T
__device__ float g_wl [BS*NP*NQ];     // word_level [b][p][q]
__device__ float g_plv[BS*NW*NP];     // patch_level [b][w][p]
__device__ float g_sim[BS*NP];        // sim [b][p]

// ---------------------------------------------------------------------------
// split helpers
// ---------------------------------------------------------------------------
__device__ __forceinline__ uint32_t pack_bf16(float lo_elem, float hi_elem) {
    uint32_t r;
    asm("cvt.rn.bf16x2.f32 %0, %1, %2;" : "=r"(r) : "f"(hi_elem), "f"(lo_elem));
    return r;
}
__device__ __forceinline__ void split4_bf16(float4 v, uint32_t* hp, uint32_t* lp) {
    float h0 = __bfloat162float(__float2bfloat16_rn(v.x));
    float h1 = __bfloat162float(__float2bfloat16_rn(v.y));
    float h2 = __bfloat162float(__float2bfloat16_rn(v.z));
    float h3 = __bfloat162float(__float2bfloat16_rn(v.w));
    hp[0] = pack_bf16(h0, h1);
    hp[1] = pack_bf16(h2, h3);
    lp[0] = pack_bf16(v.x - h0, v.y - h1);
    lp[1] = pack_bf16(v.z - h2, v.w - h3);
}
__device__ __forceinline__ uint32_t pack_f16(float lo_elem, float hi_elem) {
    uint32_t r;
    asm("cvt.rn.f16x2.f32 %0, %1, %2;" : "=r"(r) : "f"(hi_elem), "f"(lo_elem));
    return r;
}
__device__ __forceinline__ void split4_f16(float4 v, uint32_t* hp, uint32_t* lp) {
    float h0 = __half2float(__float2half_rn(v.x));
    float h1 = __half2float(__float2half_rn(v.y));
    float h2 = __half2float(__float2half_rn(v.z));
    float h3 = __half2float(__float2half_rn(v.w));
    hp[0] = pack_f16(h0, h1);
    hp[1] = pack_f16(h2, h3);
    lp[0] = pack_f16(v.x - h0, v.y - h1);
    lp[1] = pack_f16(v.z - h2, v.w - h3);
}
__device__ __forceinline__ void mma_bf16(float4& d,
    uint32_t a0, uint32_t a1, uint32_t a2, uint32_t a3,
    uint32_t b0, uint32_t b1) {
    asm volatile(
        "mma.sync.aligned.m16n8k16.row.col.f32.bf16.bf16.f32 "
        "{%0,%1,%2,%3}, {%4,%5,%6,%7}, {%8,%9}, {%0,%1,%2,%3};\n"
        : "+f"(d.x), "+f"(d.y), "+f"(d.z), "+f"(d.w)
        : "r"(a0), "r"(a1), "r"(a2), "r"(a3), "r"(b0), "r"(b1));
}
__device__ __forceinline__ void mma_f16(float4& d,
    uint32_t a0, uint32_t a1, uint32_t a2, uint32_t a3,
    uint32_t b0, uint32_t b1) {
    asm volatile(
        "mma.sync.aligned.m16n8k16.row.col.f32.f16.f16.f32 "
        "{%0,%1,%2,%3}, {%4,%5,%6,%7}, {%8,%9}, {%0,%1,%2,%3};\n"
        : "+f"(d.x), "+f"(d.y), "+f"(d.z), "+f"(d.w)
        : "r"(a0), "r"(a1), "r"(a2), "r"(a3), "r"(b0), "r"(b1));
}

// ---------------------------------------------------------------------------
// K1 v2: pl = patch2d @ L^T via fp16 2-split mma (3 products).
//   M=4608, N=768, K=768. Tile 128x96, k16 chunks (48), 2-stage.
//   256 threads = 8 warps; warp (mw 0..3, nw 0..1): rows [32mw,32mw+32),
//   cols [48nw,48nw+48). Per warp: 2 m-tiles x 6 n-tiles.
// smem (uint32 words): per stage: Ah 128*12=1536 | Al 1536 | Bh 96*12=1152 |
//   Bl 1152 = 5376 words; x2 stages = 10752 words = 43008 B.
// ---------------------------------------------------------------------------
#define K1PRS 12
#define K1_STG 5376

__global__ void __launch_bounds__(256, 2) k1_plgemm(const float* __restrict__ patch,
                                                    const float* __restrict__ L) {
    extern __shared__ float smf[];
    uint32_t* smw = (uint32_t*)smf;
    const int tid = threadIdx.x;
    const int lane = tid & 31, wid = tid >> 5;
    const int g = lane >> 2, t4 = lane & 3;
    const int mw = wid >> 1, nw = wid & 1;
    const int m0 = blockIdx.y * 128;      // 36 blocks
    const int n0 = blockIdx.x * 96;       // 8 blocks
    const float* Ap = patch + (size_t)m0 * DIM;
    const float* Bp = L + (size_t)n0 * DIM;

    // prefetch chunk 0: A 512 float4 (2/thread), B 384 float4
    float4 pa[2], pb[2];
#pragma unroll
    for (int j = 0; j < 2; j++) {
        const int pos = tid + 256 * j;        // < 512
        pa[j] = *(const float4*)&Ap[(pos >> 2) * DIM + 4 * (pos & 3)];
    }
#pragma unroll
    for (int j = 0; j < 2; j++) {
        const int pos = tid + 256 * j;
        if (pos < 384)
            pb[j] = *(const float4*)&Bp[(pos >> 2) * DIM + 4 * (pos & 3)];
    }

    float4 acc[2][6];
#pragma unroll
    for (int i = 0; i < 2; i++)
#pragma unroll
        for (int j = 0; j < 6; j++) acc[i][j] = make_float4(0.f, 0.f, 0.f, 0.f);

    for (int kc = 0; kc < 48; kc++) {
        __syncthreads();
        uint32_t* Ah = smw + (kc & 1) * K1_STG;
        uint32_t* Al = Ah + 1536;
        uint32_t* Bh = Ah + 3072;
        uint32_t* Bl = Ah + 4224;
#pragma unroll
        for (int j = 0; j < 2; j++) {
            const int pos = tid + 256 * j, r = pos >> 2, c4 = pos & 3;
            uint32_t hp[2], lp[2];
            split4_f16(pa[j], hp, lp);
            *(uint2*)&Ah[r * K1PRS + 2 * c4] = make_uint2(hp[0], hp[1]);
            *(uint2*)&Al[r * K1PRS + 2 * c4] = make_uint2(lp[0], lp[1]);
        }
#pragma unroll
        for (int j = 0; j < 2; j++) {
            const int pos = tid + 256 * j;
            if (pos < 384) {
                const int r = pos >> 2, c4 = pos & 3;
                uint32_t hp[2], lp[2];
                split4_f16(pb[j], hp, lp);
                *(uint2*)&Bh[r * K1PRS + 2 * c4] = make_uint2(hp[0], hp[1]);
                *(uint2*)&Bl[r * K1PRS + 2 * c4] = make_uint2(lp[0], lp[1]);
            }
        }
        __syncthreads();
        if (kc < 47) {
            const int kn = (kc + 1) * 16;
#pragma unroll
            for (int j = 0; j < 2; j++) {
                const int pos = tid + 256 * j;
                pa[j] = *(const float4*)&Ap[(pos >> 2) * DIM + kn + 4 * (pos & 3)];
            }
#pragma unroll
            for (int j = 0; j < 2; j++) {
                const int pos = tid + 256 * j;
                if (pos < 384)
                    pb[j] = *(const float4*)&Bp[(pos >> 2) * DIM + kn + 4 * (pos & 3)];
            }
        }
#pragma unroll
        for (int mt = 0; mt < 2; mt++) {
            const int arow = (mw * 32 + mt * 16 + g) * K1PRS + t4;
            const uint32_t ah0 = Ah[arow];
            const uint32_t ah1 = Ah[arow + 8 * K1PRS];
            const uint32_t ah2 = Ah[arow + 4];
            const uint32_t ah3 = Ah[arow + 8 * K1PRS + 4];
            const uint32_t al0 = Al[arow];
            const uint32_t al1 = Al[arow + 8 * K1PRS];
            const uint32_t al2 = Al[arow + 4];
            const uint32_t al3 = Al[arow + 8 * K1PRS + 4];
#pragma unroll
            for (int nt = 0; nt < 6; nt++) {
                const int brow = (nw * 48 + nt * 8 + g) * K1PRS + t4;
                const uint32_t bh0 = Bh[brow];
                const uint32_t bh1 = Bh[brow + 4];
                const uint32_t bl0 = Bl[brow];
                const uint32_t bl1 = Bl[brow + 4];
                mma_f16(acc[mt][nt], ah0, ah1, ah2, ah3, bh0, bh1);
                mma_f16(acc[mt][nt], ah0, ah1, ah2, ah3, bl0, bl1);
                mma_f16(acc[mt][nt], al0, al1, al2, al3, bh0, bh1);
            }
        }
    }

    // store C fragments
#pragma unroll
    for (int mt = 0; mt < 2; mt++) {
#pragma unroll
        for (int nt = 0; nt < 6; nt++) {
            const int row = m0 + mw * 32 + mt * 16 + g;
            const int col = n0 + nw * 48 + nt * 8 + 2 * t4;
            g_pl[(size_t)row * DIM + col]           = acc[mt][nt].x;
            g_pl[(size_t)row * DIM + col + 1]       = acc[mt][nt].y;
            g_pl[(size_t)(row + 8) * DIM + col]     = acc[mt][nt].z;
            g_pl[(size_t)(row + 8) * DIM + col + 1] = acc[mt][nt].w;
        }
    }
}

// ---------------------------------------------------------------------------
// K2 v5: bf16 2-split mma.sync mainloop + register-G epilogue, 2 CTAs/SM.
// (unchanged from R7)
// ---------------------------------------------------------------------------
#define SMW_BUF 8960
#define PRS 20          // pair-row stride in words

__global__ void __launch_bounds__(320, 2) k2_fine(const float* __restrict__ word,
                                                  const float* __restrict__ Ww,
                                                  const float* __restrict__ Wp) {
    extern __shared__ float sm[];
    uint32_t* smw = (uint32_t*)sm;
    float* Fs   = sm;            // 11840
    float* red  = sm + 11840;    // 2368
    float* Wws  = sm + 17920;    // 6400
    float* Wps  = sm + 24320;    // 1296
    float* cmax = sm + 25616;    // 144
    float* csum = sm + 25760;    // 144

    const int tid  = threadIdx.x;
    const int lane = tid & 31, wid = tid >> 5;
    const int g  = lane >> 2, t4 = lane & 3;
    const int ms = wid >> 1,  ns = wid & 1;        // wid 0..9
    const int b = blockIdx.y, pb = blockIdx.x;

    for (int i = tid; i < 1600; i += 320) ((float4*)Wws)[i] = ((const float4*)Ww)[i];
    for (int i = tid; i < 324;  i += 320) ((float4*)Wps)[i] = ((const float4*)Wp)[i];

    const float* Aw = word + (size_t)b * NW * DIM;
    const float* Bp = g_pl + (size_t)pb * NT * DIM;   // 144 contiguous rows

    float4 pa[2], pb4[4];
#pragma unroll
    for (int j = 0; j < 2; j++) {
        const int pos = tid + 320 * j;                 // < 640
        pa[j] = *(const float4*)&Aw[(pos >> 3) * DIM + 4 * (pos & 7)];
    }
#pragma unroll
    for (int j = 0; j < 4; j++) {
        const int pos = tid + 320 * j;
        if (pos < 1152)
            pb4[j] = *(const float4*)&Bp[(pos >> 3) * DIM + 4 * (pos & 7)];
    }

    float4 acc[9];
#pragma unroll
    for (int j = 0; j < 9; j++) acc[j] = make_float4(0.f, 0.f, 0.f, 0.f);

    for (int kc = 0; kc < 24; kc++) {
        __syncthreads();
        uint32_t* Ah = smw + (kc & 1) * SMW_BUF;
        uint32_t* Al = Ah + 1600;
        uint32_t* Bh = Ah + 3200;
        uint32_t* Bl = Ah + 6080;
#pragma unroll
        for (int j = 0; j < 2; j++) {
            const int pos = tid + 320 * j, r = pos >> 3, c4 = pos & 7;
            uint32_t hp[2], lp[2];
            split4_bf16(pa[j], hp, lp);
            *(uint2*)&Ah[r * PRS + 2 * c4] = make_uint2(hp[0], hp[1]);
            *(uint2*)&Al[r * PRS + 2 * c4] = make_uint2(lp[0], lp[1]);
        }
#pragma unroll
        for (int j = 0; j < 4; j++) {
            const int pos = tid + 320 * j;
            if (pos < 1152) {
                const int r = pos >> 3, c4 = pos & 7;
                uint32_t hp[2], lp[2];
                split4_bf16(pb4[j], hp, lp);
                *(uint2*)&Bh[r * PRS + 2 * c4] = make_uint2(hp[0], hp[1]);
                *(uint2*)&Bl[r * PRS + 2 * c4] = make_uint2(lp[0], lp[1]);
            }
        }
        __syncthreads();
        if (kc < 23) {
            const int kn = (kc + 1) * 32;
#pragma unroll
            for (int j = 0; j < 2; j++) {
                const int pos = tid + 320 * j;
                pa[j] = *(const float4*)&Aw[(pos >> 3) * DIM + kn + 4 * (pos & 7)];
            }
#pragma unroll
            for (int j = 0; j < 4; j++) {
                const int pos = tid + 320 * j;
                if (pos < 1152)
                    pb4[j] = *(const float4*)&Bp[(pos >> 3) * DIM + kn + 4 * (pos & 7)];
            }
        }
#pragma unroll
        for (int ks = 0; ks < 2; ks++) {
            const int arow = (16 * ms + g) * PRS + ks * 8 + t4;
            const uint32_t ah0 = Ah[arow];
            const uint32_t ah1 = Ah[arow + 8 * PRS];
            const uint32_t ah2 = Ah[arow + 4];
            const uint32_t ah3 = Ah[arow + 8 * PRS + 4];
            const uint32_t al0 = Al[arow];
            const uint32_t al1 = Al[arow + 8 * PRS];
            const uint32_t al2 = Al[arow + 4];
            const uint32_t al3 = Al[arow + 8 * PRS + 4];
#pragma unroll
            for (int nt = 0; nt < 9; nt++) {
                const int brow = (72 * ns + 8 * nt + g) * PRS + ks * 8 + t4;
                const uint32_t bh0 = Bh[brow];
                const uint32_t bh1 = Bh[brow + 4];
                const uint32_t bl0 = Bl[brow];
                const uint32_t bl1 = Bl[brow + 4];
                mma_bf16(acc[nt], ah0, ah1, ah2, ah3, bh0, bh1);
                mma_bf16(acc[nt], ah0, ah1, ah2, ah3, bl0, bl1);
                mma_bf16(acc[nt], al0, al1, al2, al3, bh0, bh1);
            }
        }
    }
    __syncthreads();

#pragma unroll
    for (int nt = 0; nt < 9; nt++) {
        const int row = 16 * ms + g, col = 72 * ns + 8 * nt + 2 * t4;
        Fs[row * FS + col]           = acc[nt].x;
        Fs[row * FS + col + 1]       = acc[nt].y;
        Fs[(row + 8) * FS + col]     = acc[nt].z;
        Fs[(row + 8) * FS + col + 1] = acc[nt].w;
    }
    __syncthreads();

    if (tid < NT) {
        float m = -1e30f;
        for (int w = 0; w < NW; w++) m = fmaxf(m, Fs[w * FS + tid]);
        float s = 0.0f;
        for (int w = 0; w < NW; w++) s += __expf((Fs[w * FS + tid] - m) * TAU_INV);
        cmax[tid] = m;
        csum[tid] = s;
    }
    float ga[5][9];
    if (tid < 256) {
        const int tx = tid & 15, ty = tid >> 4;
#pragma unroll
        for (int i = 0; i < 5; i++)
#pragma unroll
            for (int j = 0; j < 9; j++) ga[i][j] = 0.0f;
        for (int v4 = 0; v4 < 20; v4++) {
            float aa[5][4];
#pragma unroll
            for (int i = 0; i < 5; i++) {
                float4 a4 = *(float4*)&Wws[(ty + 16 * i) * 80 + 4 * v4];
                aa[i][0] = a4.x; aa[i][1] = a4.y; aa[i][2] = a4.z; aa[i][3] = a4.w;
            }
#pragma unroll
            for (int vv = 0; vv < 4; vv++) {
                const int v = 4 * v4 + vv;
                float bv[9];
#pragma unroll
                for (int j = 0; j < 9; j++) bv[j] = Fs[v * FS + tx + 16 * j];
#pragma unroll
                for (int i = 0; i < 5; i++)
#pragma unroll
                    for (int j = 0; j < 9; j++) ga[i][j] += aa[i][vv] * bv[j];
            }
        }
    }
    __syncthreads();

    if (tid < 256) {
        const int tx = tid & 15, ty = tid >> 4;
#pragma unroll
        for (int j = 0; j < 9; j++) {
            const int c = tx + 16 * j;
            const float m = cmax[c];
            float part = 0.0f;
#pragma unroll
            for (int i = 0; i < 5; i++)
                part += __expf((Fs[(ty + 16 * i) * FS + c] - m) * TAU_INV) * ga[i][j];
            red[ty * FS + c] = part;
        }
    }
    __syncthreads();

    if (tid < NT) {
        float a = 0.0f;
#pragma unroll
        for (int t = 0; t < 16; t++) a += red[t * FS + tid];
        g_wl[(size_t)b * (NP * NQ) + pb * NT + tid] = a / csum[tid];
    }

    for (int pr = tid; pr < NW * PT; pr += 320) {
        const int w = pr >> 2, p = pr & 3;
        const float* frow = &Fs[w * FS + p * NQ];
        float fr[NQ];
#pragma unroll
        for (int c = 0; c < 9; c++) *(float4*)&fr[4 * c] = *(const float4*)&frow[4 * c];
        float m = fr[0];
#pragma unroll
        for (int q = 1; q < NQ; q++) m = fmaxf(m, fr[q]);
        float s = 0.0f, a = 0.0f;
        for (int q = 0; q < NQ; q++) {
            float u = 0.0f;
#pragma unroll
            for (int rv = 0; rv < 9; rv++) {
                float4 w4 = *(float4*)&Wps[q * NQ + 4 * rv];
                u += w4.x * fr[4 * rv] + w4.y * fr[4 * rv + 1] +
                     w4.z * fr[4 * rv + 2] + w4.w * fr[4 * rv + 3];
            }
            const float e = __expf((fr[q] - m) * TAU_INV);
            s += e;
            a += e * u;
        }
        g_plv[(size_t)b * (NW * NP) + w * NP + pb * PT + p] = a / s;
    }
}

// ---------------------------------------------------------------------------
// K3: per b: s2p/p2w second-level reductions -> sim[b][p]
// ---------------------------------------------------------------------------
__global__ void __launch_bounds__(128) k3_stage2(const float* __restrict__ Ww2,
                                                 const float* __restrict__ Wp2) {
    extern __shared__ float sm[];
    float* wls = sm;            // 4608
    float* pls = sm + 4608;     // 10240
    float* W2s = sm + 14848;    // 6400
    float* P2s = sm + 21248;    // 1296
    const int b = blockIdx.x, tid = threadIdx.x;

    const float4* s1 = (const float4*)(g_wl + (size_t)b * (NP * NQ));
    for (int i = tid; i < 1152; i += 128) ((float4*)wls)[i] = s1[i];
    const float4* s2 = (const float4*)(g_plv + (size_t)b * (NW * NP));
    for (int i = tid; i < 2560; i += 128) ((float4*)pls)[i] = s2[i];
    for (int i = tid; i < 1600; i += 128) ((float4*)W2s)[i] = ((const float4*)Ww2)[i];
    for (int i = tid; i < 324;  i += 128) ((float4*)P2s)[i] = ((const float4*)Wp2)[i];
    __syncthreads();

    const int p = tid;
    float fr[NQ];
#pragma unroll
    for (int c = 0; c < 9; c++) *(float4*)&fr[4 * c] = *(float4*)&wls[p * NQ + 4 * c];
    float m = fr[0];
#pragma unroll
    for (int q = 1; q < NQ; q++) m = fmaxf(m, fr[q]);
    float s = 0.0f, a = 0.0f;
    for (int q = 0; q < NQ; q++) {
        float u = 0.0f;
#pragma unroll
        for (int rv = 0; rv < 9; rv++) {
            float4 w4 = *(float4*)&P2s[q * NQ + 4 * rv];
            u += w4.x * fr[4 * rv] + w4.y * fr[4 * rv + 1] +
                 w4.z * fr[4 * rv + 2] + w4.w * fr[4 * rv + 3];
        }
        const float e = __expf((fr[q] - m) * TAU_INV);
        s += e; a += e * u;
    }
    const float s2p = a / s;

    float fw[NW];
    for (int w = 0; w < NW; w++) fw[w] = pls[w * NP + p];
    m = fw[0];
#pragma unroll
    for (int w = 1; w < NW; w++) m = fmaxf(m, fw[w]);
    s = 0.0f; a = 0.0f;
    for (int w = 0; w < NW; w++) {
        float u = 0.0f;
#pragma unroll
        for (int v4 = 0; v4 < 20; v4++) {
            float4 w4 = *(float4*)&W2s[w * NW + 4 * v4];
            u += w4.x * fw[4 * v4] + w4.y * fw[4 * v4 + 1] +
                 w4.z * fw[4 * v4 + 2] + w4.w * fw[4 * v4 + 3];
        }
        const float e = __expf((fw[w] - m) * TAU_INV);
        s += e; a += e * u;
    }
    const float p2w = a / s;

    g_sim[b * NP + p] = 0.5f * (s2p + p2w);
}

// ---------------------------------------------------------------------------
// K4 v2: 256 threads — row-LSE and col-LSE computed concurrently.
// ---------------------------------------------------------------------------
__global__ void __launch_bounds__(256) k4_loss(float* __restrict__ out) {
    extern __shared__ float sm[];
    float* sims = sm;                   // 128*129 (padded)
    float* lse  = sm + 128 * 129;       // 256
    float* red  = sm + 128 * 129 + 256; // 128
    const int tid = threadIdx.x;
    for (int i = tid; i < BS * NP; i += 256) {
        const int r = i >> 7, c = i & 127;
        sims[r * 129 + c] = g_sim[i];
    }
    __syncthreads();
    const int i = tid & 127;
    if (tid < 128) {
        float m = -1e30f;
        for (int j = 0; j < 128; j++) m = fmaxf(m, sims[i * 129 + j]);
        float s = 0.0f;
        for (int j = 0; j < 128; j++) s += expf(sims[i * 129 + j] - m);
        lse[i] = m + logf(s);
    } else {
        float m = -1e30f;
        for (int j = 0; j < 128; j++) m = fmaxf(m, sims[j * 129 + i]);
        float s = 0.0f;
        for (int j = 0; j < 128; j++) s += expf(sims[j * 129 + i] - m);
        lse[128 + i] = m + logf(s);
    }
    __syncthreads();
    if (tid < 128)
        red[i] = sims[i * 129 + i] - 0.5f * (lse[i] + lse[128 + i]);
    __syncthreads();
    for (int st = 64; st > 0; st >>= 1) {
        if (tid < st) red[tid] += red[tid + st];
        __syncthreads();
    }
    if (tid == 0) out[0] = -red[0] / 128.0f;
}

// ---------------------------------------------------------------------------
extern "C" void kernel_launch(void* const* d_in, const int* in_sizes, int n_in,
                              void* d_out, int out_size) {
    const float* patch = (const float*)d_in[0];  // (128, 36, 768)
    const float* word  = (const float*)d_in[1];  // (128, 80, 768)
    const float* L     = (const float*)d_in[2];  // (768, 768)
    const float* Ww    = (const float*)d_in[3];  // (80, 80)
    const float* Wp    = (const float*)d_in[4];  // (36, 36)
    const float* Ww2   = (const float*)d_in[5];  // (80, 80)
    const float* Wp2   = (const float*)d_in[6];  // (36, 36)
    float* out = (float*)d_out;

    const int smem_k1 = 10752 * 4;
    const int smem_k2 = 25904 * 4;
    const int smem_k3 = 22544 * 4;
    const int smem_k4 = (128 * 129 + 256 + 128) * 4;
    cudaFuncSetAttribute(k1_plgemm, cudaFuncAttributeMaxDynamicSharedMemorySize, smem_k1);
    cudaFuncSetAttribute(k2_fine,   cudaFuncAttributeMaxDynamicSharedMemorySize, smem_k2);
    cudaFuncSetAttribute(k3_stage2, cudaFuncAttributeMaxDynamicSharedMemorySize, smem_k3);
    cudaFuncSetAttribute(k4_loss,   cudaFuncAttributeMaxDynamicSharedMemorySize, smem_k4);

    k1_plgemm<<<dim3(8, 36), 256, smem_k1>>>(patch, L);
    k2_fine<<<dim3(NP / PT, BS), 320, smem_k2>>>(word, Ww, Wp);
    k3_stage2<<<BS, 128, smem_k3>>>(Ww2, Wp2);
    k4_loss<<<1, 256, smem_k4>>>(out);
}